// round 15
// baseline (speedup 1.0000x reference)
#include <cuda_runtime.h>
#include <cuda_bf16.h>
#include <math.h>

#define BB 4
#define CHW 1048576LL
#define KC 2304

__device__ float g_a  [BB*CHW];
__device__ float g_h  [BB*CHW];
__device__ float g_xr [BB*CHW];
__device__ float g_gb [BB*512];
__device__ float g_part[BB*32*4*2];
__device__ float g_w1t[256*KC];
__device__ float g_w2t[256*KC];
__device__ __nv_bfloat16 g_ah  [BB*CHW];
__device__ __nv_bfloat16 g_qwb [768*256];
__device__ __nv_bfloat16 g_owb [256*256];
__device__ __nv_bfloat16 g_qkvb[BB*3*CHW];
__device__ __nv_bfloat16 g_vtb [BB*CHW];
__device__ __nv_bfloat16 g_aob [BB*CHW];

__device__ __forceinline__ unsigned smem_u32(const void* p){
    unsigned r;
    asm("{ .reg .u64 t; cvta.to.shared.u64 t, %1; cvt.u32.u64 %0, t; }" : "=r"(r) : "l"(p));
    return r;
}
__device__ __forceinline__ float rnd_tf32(float f){
    unsigned r; asm("cvt.rna.tf32.f32 %0, %1;" : "=r"(r) : "f"(f));
    return __uint_as_float(r);
}
__device__ __forceinline__ unsigned swz(unsigned off){ return off ^ ((off >> 3) & 0x70u); }

#define LDMX4(r, addr) \
    asm volatile("ldmatrix.sync.aligned.m8n8.x4.shared.b16 {%0,%1,%2,%3}, [%4];" \
        : "=r"((r)[0]),"=r"((r)[1]),"=r"((r)[2]),"=r"((r)[3]) : "r"(addr))
#define MMAT(c, a, b0, b1) \
    asm volatile("mma.sync.aligned.m16n8k8.row.col.f32.tf32.tf32.f32 " \
        "{%0,%1,%2,%3},{%4,%5,%6,%7},{%8,%9},{%0,%1,%2,%3};" \
        : "+f"((c)[0]),"+f"((c)[1]),"+f"((c)[2]),"+f"((c)[3]) \
        : "r"((a)[0]),"r"((a)[1]),"r"((a)[2]),"r"((a)[3]),"r"(b0),"r"(b1))
#define MMAB(c, a, b0, b1) \
    asm volatile("mma.sync.aligned.m16n8k16.row.col.f32.bf16.bf16.f32 " \
        "{%0,%1,%2,%3},{%4,%5,%6,%7},{%8,%9},{%0,%1,%2,%3};" \
        : "+f"((c)[0]),"+f"((c)[1]),"+f"((c)[2]),"+f"((c)[3]) \
        : "r"((a)[0]),"r"((a)[1]),"r"((a)[2]),"r"((a)[3]),"r"(b0),"r"(b1))

// ====== tf32 conv GEMM (implicit im2col), 256x128 tile, 4-stage; res in NCHW ======
__global__ void __launch_bounds__(256, 1) gemm_conv(
    const float* __restrict__ A, const float* __restrict__ B,
    float* __restrict__ Y,
    const float* __restrict__ bias, const float* __restrict__ filmB,
    const float* __restrict__ resN)
{
    extern __shared__ char smem[];
    unsigned sbase = smem_u32(smem);
    int tid = threadIdx.x, lane = tid & 31, wid = tid >> 5;
    int warp_m = wid & 3, warp_n = wid >> 2;
    int b = blockIdx.z;
    int m0 = blockIdx.x * 256, n0 = blockIdx.y * 128;
    const float* Ab = A + (size_t)b * CHW;
    const float* Bb = B + (size_t)n0 * KC;

    float acc[4][8][4];
    #pragma unroll
    for (int mi = 0; mi < 4; mi++)
        #pragma unroll
        for (int ni = 0; ni < 8; ni++)
            #pragma unroll
            for (int e = 0; e < 4; e++) acc[mi][ni][e] = 0.f;

#define ISSUE_C(st, kb) { \
    unsigned ab_ = sbase + (st) * 32768u; \
    unsigned bb_ = sbase + 131072u + (st) * 16384u; \
    int t_ = (kb) >> 3; int kh_ = t_ / 3 - 1; int kw_ = t_ - (t_ / 3) * 3 - 1; \
    int cb_ = ((kb) & 7) * 32; \
    _Pragma("unroll") \
    for (int i_ = 0; i_ < 8; i_++) { \
        int c_ = tid + i_ * 256; int row_ = c_ >> 3, seg_ = c_ & 7; \
        int p_ = m0 + row_; \
        int h2_ = (p_ >> 6) + kh_, w2_ = (p_ & 63) + kw_; \
        int ok_ = ((unsigned)h2_ < 64u) && ((unsigned)w2_ < 64u); \
        int hc_ = ok_ ? h2_ : 0, wc_ = ok_ ? w2_ : 0; \
        unsigned sz_ = ok_ ? 16u : 0u; \
        const float* src_ = Ab + (size_t)((hc_ << 6) + wc_) * 256 + cb_ + seg_ * 4; \
        unsigned d_ = ab_ + swz((unsigned)row_ * 128u + seg_ * 16u); \
        asm volatile("cp.async.cg.shared.global [%0], [%1], 16, %2;" :: "r"(d_), "l"(src_), "r"(sz_)); } \
    { const float* Bs_ = Bb + (kb) * 32; \
    _Pragma("unroll") \
    for (int i_ = 0; i_ < 4; i_++) { \
        int c_ = tid + i_ * 256; int row_ = c_ >> 3, seg_ = c_ & 7; \
        unsigned d_ = bb_ + swz((unsigned)row_ * 128u + seg_ * 16u); \
        asm volatile("cp.async.cg.shared.global [%0], [%1], 16;" :: "r"(d_), "l"(Bs_ + (size_t)row_ * KC + seg_ * 4)); } } \
    asm volatile("cp.async.commit_group;"); }

    const int nkb = KC >> 5;
    ISSUE_C(0, 0); ISSUE_C(1, 1); ISSUE_C(2, 2);

    unsigned arow = (unsigned)(warp_m * 64 + (lane & 7) + (lane & 8));
    unsigned acol = (lane & 16) ? 16u : 0u;
    unsigned brow = (unsigned)(warp_n * 64 + (lane & 7) + ((lane & 16) >> 1));
    unsigned bcol = (lane & 8) ? 16u : 0u;

    for (int kb = 0; kb < nkb; kb++) {
        int st = kb & 3;
        asm volatile("cp.async.wait_group 2;" ::: "memory");
        __syncthreads();
        unsigned ab_ = sbase + st * 32768u;
        unsigned bb_ = sbase + 131072u + st * 16384u;
        #pragma unroll
        for (int k8 = 0; k8 < 4; k8++) {
            unsigned kc = k8 * 32u;
            unsigned af[4][4], bf[4][4];
            #pragma unroll
            for (int mi = 0; mi < 4; mi++)
                LDMX4(af[mi], ab_ + swz((arow + mi * 16u) * 128u + kc + acol));
            #pragma unroll
            for (int pi = 0; pi < 4; pi++)
                LDMX4(bf[pi], bb_ + swz((brow + pi * 16u) * 128u + kc + bcol));
            #pragma unroll
            for (int mi = 0; mi < 4; mi++)
                #pragma unroll
                for (int pi = 0; pi < 4; pi++) {
                    MMAT(acc[mi][2*pi],   af[mi], bf[pi][0], bf[pi][1]);
                    MMAT(acc[mi][2*pi+1], af[mi], bf[pi][2], bf[pi][3]);
                }
        }
        __syncthreads();
        if (kb + 3 < nkb) { ISSUE_C((kb + 3) & 3, kb + 3); }
        else asm volatile("cp.async.commit_group;");
    }

    const float* fg = filmB ? (filmB + (size_t)b * 512) : (const float*)0;
    const float* Rb = resN ? (resN + (size_t)b * CHW) : (const float*)0;
    int g = lane >> 2, t = lane & 3;
    #pragma unroll
    for (int mi = 0; mi < 4; mi++) {
        #pragma unroll
        for (int r = 0; r < 2; r++) {
            int m = m0 + warp_m * 64 + mi * 16 + g + r * 8;
            float* Yr = Y + (size_t)b * CHW + (size_t)m * 256;
            #pragma unroll
            for (int ni = 0; ni < 8; ni++) {
                int n = n0 + warp_n * 64 + ni * 8 + 2 * t;
                float v0 = acc[mi][ni][2*r]     + bias[n];
                float v1 = acc[mi][ni][2*r + 1] + bias[n + 1];
                if (fg) {
                    v0 = (1.f + fg[n]) * v0 + fg[256 + n];
                    v1 = (1.f + fg[n + 1]) * v1 + fg[256 + n + 1];
                }
                if (Rb) {
                    v0 += Rb[(size_t)n * 4096 + m];
                    v1 += Rb[(size_t)(n + 1) * 4096 + m];
                }
                *(float2*)&Yr[n] = make_float2(v0, v1);
            }
        }
    }
}

// ====== bf16 GEMM (qkv proj); grid (16, 6, BB) ======
__global__ void __launch_bounds__(256, 1) gemm_bf(
    const __nv_bfloat16* __restrict__ A, int lda, long long sA,
    const __nv_bfloat16* __restrict__ B, int ldb,
    __nv_bfloat16* __restrict__ Yb, int ldy, long long sY, int K)
{
    extern __shared__ char smem[];
    unsigned sbase = smem_u32(smem);
    int tid = threadIdx.x, lane = tid & 31, wid = tid >> 5;
    int warp_m = wid & 3, warp_n = wid >> 2;
    int b = blockIdx.z;
    int m0 = blockIdx.x * 256, n0 = blockIdx.y * 128;
    const __nv_bfloat16* Ab = A + sA * b + (size_t)m0 * lda;
    const __nv_bfloat16* Bb = B + (size_t)n0 * ldb;

    float acc[4][8][4];
    #pragma unroll
    for (int mi = 0; mi < 4; mi++)
        #pragma unroll
        for (int ni = 0; ni < 8; ni++)
            #pragma unroll
            for (int e = 0; e < 4; e++) acc[mi][ni][e] = 0.f;

#define ISSUE_B(st, kb) { \
    unsigned ab_ = sbase + (st) * 32768u; \
    unsigned bb_ = sbase + 98304u + (st) * 16384u; \
    const __nv_bfloat16* As_ = Ab + (kb) * 64; \
    const __nv_bfloat16* Bs_ = Bb + (kb) * 64; \
    _Pragma("unroll") \
    for (int i_ = 0; i_ < 8; i_++) { \
        int c_ = tid + i_ * 256; int row_ = c_ >> 3, seg_ = c_ & 7; \
        unsigned d_ = ab_ + swz((unsigned)row_ * 128u + seg_ * 16u); \
        asm volatile("cp.async.cg.shared.global [%0], [%1], 16;" :: "r"(d_), "l"(As_ + (size_t)row_ * lda + seg_ * 8)); } \
    _Pragma("unroll") \
    for (int i_ = 0; i_ < 4; i_++) { \
        int c_ = tid + i_ * 256; int row_ = c_ >> 3, seg_ = c_ & 7; \
        unsigned d_ = bb_ + swz((unsigned)row_ * 128u + seg_ * 16u); \
        asm volatile("cp.async.cg.shared.global [%0], [%1], 16;" :: "r"(d_), "l"(Bs_ + (size_t)row_ * ldb + seg_ * 8)); } \
    asm volatile("cp.async.commit_group;"); }

    int nkb = K >> 6;
    ISSUE_B(0, 0);
    ISSUE_B(1, 1);

    unsigned arow = (unsigned)(warp_m * 64 + (lane & 7) + (lane & 8));
    unsigned acol = (lane & 16) ? 16u : 0u;
    unsigned brow = (unsigned)(warp_n * 64 + (lane & 7) + ((lane & 16) >> 1));
    unsigned bcol = (lane & 8) ? 16u : 0u;

    for (int kb = 0; kb < nkb; kb++) {
        int st = kb % 3;
        asm volatile("cp.async.wait_group 1;" ::: "memory");
        __syncthreads();
        unsigned ab_ = sbase + st * 32768u;
        unsigned bb_ = sbase + 98304u + st * 16384u;
        #pragma unroll
        for (int k16 = 0; k16 < 4; k16++) {
            unsigned kc = k16 * 32u;
            unsigned af[4][4], bf[4][4];
            #pragma unroll
            for (int mi = 0; mi < 4; mi++)
                LDMX4(af[mi], ab_ + swz((arow + mi * 16u) * 128u + kc + acol));
            #pragma unroll
            for (int pi = 0; pi < 4; pi++)
                LDMX4(bf[pi], bb_ + swz((brow + pi * 16u) * 128u + kc + bcol));
            #pragma unroll
            for (int mi = 0; mi < 4; mi++)
                #pragma unroll
                for (int pi = 0; pi < 4; pi++) {
                    MMAB(acc[mi][2*pi],   af[mi], bf[pi][0], bf[pi][1]);
                    MMAB(acc[mi][2*pi+1], af[mi], bf[pi][2], bf[pi][3]);
                }
        }
        __syncthreads();
        if (kb + 2 < nkb) { ISSUE_B((kb + 2) % 3, kb + 2); }
        else asm volatile("cp.async.commit_group;");
    }

    int g = lane >> 2, t = lane & 3;
    #pragma unroll
    for (int mi = 0; mi < 4; mi++) {
        #pragma unroll
        for (int r = 0; r < 2; r++) {
            int m = m0 + warp_m * 64 + mi * 16 + g + r * 8;
            #pragma unroll
            for (int ni = 0; ni < 8; ni++) {
                int n = n0 + warp_n * 64 + ni * 8 + 2 * t;
                __nv_bfloat16* Yp = Yb + sY * b + (size_t)m * ldy + n;
                *(__nv_bfloat162*)Yp = __floats2bfloat162_rn(acc[mi][ni][2*r], acc[mi][ni][2*r+1]);
            }
        }
    }
}

// ====== bf16 out-projection GEMM, NCHW transposed epilogue; grid (16, 2, BB), K=256 ======
__global__ void __launch_bounds__(256, 1) gemm_out(
    const __nv_bfloat16* __restrict__ A,
    const __nv_bfloat16* __restrict__ B,
    float* __restrict__ Y,
    const float* __restrict__ bias, const float* __restrict__ res)
{
    extern __shared__ char smem[];
    unsigned sbase = smem_u32(smem);
    int tid = threadIdx.x, lane = tid & 31, wid = tid >> 5;
    int warp_m = wid & 3, warp_n = wid >> 2;
    int b = blockIdx.z;
    int m0 = blockIdx.x * 256, n0 = blockIdx.y * 128;
    const __nv_bfloat16* Ab = A + (size_t)b * CHW + (size_t)m0 * 256;
    const __nv_bfloat16* Bb = B + (size_t)n0 * 256;

    float acc[4][8][4];
    #pragma unroll
    for (int mi = 0; mi < 4; mi++)
        #pragma unroll
        for (int ni = 0; ni < 8; ni++)
            #pragma unroll
            for (int e = 0; e < 4; e++) acc[mi][ni][e] = 0.f;

#define ISSUE_O(st, kb) { \
    unsigned ab_ = sbase + (st) * 32768u; \
    unsigned bb_ = sbase + 98304u + (st) * 16384u; \
    const __nv_bfloat16* As_ = Ab + (kb) * 64; \
    const __nv_bfloat16* Bs_ = Bb + (kb) * 64; \
    _Pragma("unroll") \
    for (int i_ = 0; i_ < 8; i_++) { \
        int c_ = tid + i_ * 256; int row_ = c_ >> 3, seg_ = c_ & 7; \
        unsigned d_ = ab_ + swz((unsigned)row_ * 128u + seg_ * 16u); \
        asm volatile("cp.async.cg.shared.global [%0], [%1], 16;" :: "r"(d_), "l"(As_ + (size_t)row_ * 256 + seg_ * 8)); } \
    _Pragma("unroll") \
    for (int i_ = 0; i_ < 4; i_++) { \
        int c_ = tid + i_ * 256; int row_ = c_ >> 3, seg_ = c_ & 7; \
        unsigned d_ = bb_ + swz((unsigned)row_ * 128u + seg_ * 16u); \
        asm volatile("cp.async.cg.shared.global [%0], [%1], 16;" :: "r"(d_), "l"(Bs_ + (size_t)row_ * 256 + seg_ * 8)); } \
    asm volatile("cp.async.commit_group;"); }

    ISSUE_O(0, 0);
    ISSUE_O(1, 1);

    unsigned arow = (unsigned)(warp_m * 64 + (lane & 7) + (lane & 8));
    unsigned acol = (lane & 16) ? 16u : 0u;
    unsigned brow = (unsigned)(warp_n * 64 + (lane & 7) + ((lane & 16) >> 1));
    unsigned bcol = (lane & 8) ? 16u : 0u;

    for (int kb = 0; kb < 4; kb++) {
        int st = kb % 3;
        asm volatile("cp.async.wait_group 1;" ::: "memory");
        __syncthreads();
        unsigned ab_ = sbase + st * 32768u;
        unsigned bb_ = sbase + 98304u + st * 16384u;
        #pragma unroll
        for (int k16 = 0; k16 < 4; k16++) {
            unsigned kc = k16 * 32u;
            unsigned af[4][4], bf[4][4];
            #pragma unroll
            for (int mi = 0; mi < 4; mi++)
                LDMX4(af[mi], ab_ + swz((arow + mi * 16u) * 128u + kc + acol));
            #pragma unroll
            for (int pi = 0; pi < 4; pi++)
                LDMX4(bf[pi], bb_ + swz((brow + pi * 16u) * 128u + kc + bcol));
            #pragma unroll
            for (int mi = 0; mi < 4; mi++)
                #pragma unroll
                for (int pi = 0; pi < 4; pi++) {
                    MMAB(acc[mi][2*pi],   af[mi], bf[pi][0], bf[pi][1]);
                    MMAB(acc[mi][2*pi+1], af[mi], bf[pi][2], bf[pi][3]);
                }
        }
        __syncthreads();
        if (kb + 2 < 4) { ISSUE_O((kb + 2) % 3, kb + 2); }
        else asm volatile("cp.async.commit_group;");
    }

    __syncthreads();
    float* sw = (float*)smem + wid * (64 * 65);
    const float* Rb = res + (size_t)b * CHW;
    int g = lane >> 2, t = lane & 3;
    #pragma unroll
    for (int mi = 0; mi < 4; mi++) {
        #pragma unroll
        for (int r = 0; r < 2; r++) {
            int ml = mi * 16 + g + r * 8;
            int m = m0 + warp_m * 64 + ml;
            #pragma unroll
            for (int ni = 0; ni < 8; ni++) {
                int nl = ni * 8 + 2 * t;
                int n = n0 + warp_n * 64 + nl;
                sw[ml * 65 + nl]     = acc[mi][ni][2*r]     + bias[n]     + Rb[(size_t)m * 256 + n];
                sw[ml * 65 + nl + 1] = acc[mi][ni][2*r + 1] + bias[n + 1] + Rb[(size_t)m * 256 + n + 1];
            }
        }
    }
    __syncwarp();
    int m_base = m0 + warp_m * 64, n_base = n0 + warp_n * 64;
    float* Yb_ = Y + (size_t)b * CHW;
    for (int row = 0; row < 64; row++) {
        float2 w = make_float2(sw[(lane * 2) * 65 + row], sw[(lane * 2 + 1) * 65 + row]);
        *(float2*)&Yb_[(size_t)(n_base + row) * 4096 + m_base + lane * 2] = w;
    }
}

// ====== fused flash attention (bf16); grid (32, BB), block 512 ======
#define FA_SQ 0u
#define FA_SK 65536u
#define FA_SV 131072u
#define FA_SP 196608u
#define FA_SM 212992u
#define FA_SL 213504u
#define FA_RM 214016u
#define FA_RS 215040u
#define FA_SMEM 216064
__global__ void __launch_bounds__(512, 1) flash_attn(
    const __nv_bfloat16* __restrict__ qkv, const __nv_bfloat16* __restrict__ vt,
    __nv_bfloat16* __restrict__ ao)
{
    extern __shared__ char smem[];
    unsigned sb = smem_u32(smem);
    float* fSM = (float*)(smem + FA_SM);
    float* fSL = (float*)(smem + FA_SL);
    float* fRM = (float*)(smem + FA_RM);
    float* fRS = (float*)(smem + FA_RS);
    int tid = threadIdx.x, lane = tid & 31, wid = tid >> 5;
    int warp_m = wid & 7, warp_n = wid >> 3;
    int b = blockIdx.y, q0 = blockIdx.x * 128;
    const __nv_bfloat16* qb = qkv + (size_t)b * 3 * CHW;
    const __nv_bfloat16* kb = qb + 256;
    const __nv_bfloat16* vb = vt + (size_t)b * CHW;
    int g = lane >> 2, t = lane & 3;
    unsigned arow_l = (unsigned)((lane & 7) + (lane & 8));
    unsigned acol = (lane & 16) ? 16u : 0u;
    unsigned brow_l = (unsigned)((lane & 7) + ((lane & 16) >> 1));
    unsigned bcol = (lane & 8) ? 16u : 0u;

#define PAIR_BAR() asm volatile("bar.sync %0, 64;" :: "r"(1 + warp_m) : "memory")

#define FA_KV(bufv, jv) { \
    _Pragma("unroll") \
    for (int i_ = 0; i_ < 4; i_++) { \
        int idx = tid + i_ * 512; int ch = idx >> 9, row = (idx >> 3) & 63, seg = idx & 7; \
        unsigned d_ = sb + FA_SK + (bufv) * 32768u + ch * 8192u + swz((unsigned)row * 128u + seg * 16u); \
        const __nv_bfloat16* s_ = kb + (size_t)((jv) + row) * 768 + ch * 64 + seg * 8; \
        asm volatile("cp.async.cg.shared.global [%0], [%1], 16;" :: "r"(d_), "l"(s_)); } \
    _Pragma("unroll") \
    for (int i_ = 0; i_ < 4; i_++) { \
        int idx = tid + i_ * 512; int row = idx >> 3, seg = idx & 7; \
        unsigned d_ = sb + FA_SV + (bufv) * 32768u + swz((unsigned)row * 128u + seg * 16u); \
        const __nv_bfloat16* s_ = vb + (size_t)row * 4096 + (jv) + seg * 8; \
        asm volatile("cp.async.cg.shared.global [%0], [%1], 16;" :: "r"(d_), "l"(s_)); } }

    #pragma unroll
    for (int i_ = 0; i_ < 8; i_++) {
        int idx = tid + i_ * 512; int ch = idx >> 10, row = (idx >> 3) & 127, seg = idx & 7;
        unsigned d_ = sb + FA_SQ + ch * 16384u + swz((unsigned)row * 128u + seg * 16u);
        const __nv_bfloat16* s_ = qb + (size_t)(q0 + row) * 768 + ch * 64 + seg * 8;
        asm volatile("cp.async.cg.shared.global [%0], [%1], 16;" :: "r"(d_), "l"(s_));
    }
    FA_KV(0, 0);
    asm volatile("cp.async.commit_group;");
    FA_KV(1, 64);
    asm volatile("cp.async.commit_group;");
    if (tid < 128) { fSM[tid] = -1e30f; fSL[tid] = 0.f; }

    float accO[16][4];
    #pragma unroll
    for (int ni = 0; ni < 16; ni++)
        #pragma unroll
        for (int e = 0; e < 4; e++) accO[ni][e] = 0.f;

    int r0 = warp_m * 16 + g, r1 = r0 + 8;

    for (int it = 0; it < 64; it++) {
        int buf = it & 1;
        asm volatile("cp.async.wait_group 1;" ::: "memory");
        __syncthreads();
        float accS[4][4];
        #pragma unroll
        for (int ni = 0; ni < 4; ni++)
            #pragma unroll
            for (int e = 0; e < 4; e++) accS[ni][e] = 0.f;
        unsigned kbase = sb + FA_SK + buf * 32768u;
        #pragma unroll
        for (int kst = 0; kst < 16; kst++) {
            unsigned ch = kst >> 2, kc = (kst & 3) * 32u;
            unsigned af[4], bf0[4], bf1[4];
            LDMX4(af, sb + FA_SQ + ch * 16384u + swz((warp_m * 16 + arow_l) * 128u + kc + acol));
            LDMX4(bf0, kbase + ch * 8192u + swz((warp_n * 32 + brow_l) * 128u + kc + bcol));
            LDMX4(bf1, kbase + ch * 8192u + swz((warp_n * 32 + 16 + brow_l) * 128u + kc + bcol));
            MMAB(accS[0], af, bf0[0], bf0[1]); MMAB(accS[1], af, bf0[2], bf0[3]);
            MMAB(accS[2], af, bf1[0], bf1[1]); MMAB(accS[3], af, bf1[2], bf1[3]);
        }
        #pragma unroll
        for (int ni = 0; ni < 4; ni++)
            #pragma unroll
            for (int e = 0; e < 4; e++) accS[ni][e] *= 0.0625f;
        float pm0 = -1e30f, pm1 = -1e30f;
        #pragma unroll
        for (int ni = 0; ni < 4; ni++) {
            pm0 = fmaxf(pm0, fmaxf(accS[ni][0], accS[ni][1]));
            pm1 = fmaxf(pm1, fmaxf(accS[ni][2], accS[ni][3]));
        }
        pm0 = fmaxf(pm0, __shfl_xor_sync(~0u, pm0, 1)); pm0 = fmaxf(pm0, __shfl_xor_sync(~0u, pm0, 2));
        pm1 = fmaxf(pm1, __shfl_xor_sync(~0u, pm1, 1)); pm1 = fmaxf(pm1, __shfl_xor_sync(~0u, pm1, 2));
        if (t == 0) { fRM[warp_n * 128 + r0] = pm0; fRM[warp_n * 128 + r1] = pm1; }
        PAIR_BAR();
        float mo0 = fSM[r0], mo1 = fSM[r1];
        float mn0 = fmaxf(mo0, fmaxf(fRM[r0], fRM[128 + r0]));
        float mn1 = fmaxf(mo1, fmaxf(fRM[r1], fRM[128 + r1]));
        float al0 = __expf(mo0 - mn0), al1 = __expf(mo1 - mn1);
        float ps0 = 0.f, ps1 = 0.f;
        #pragma unroll
        for (int ni = 0; ni < 4; ni++) {
            float p00 = __expf(accS[ni][0] - mn0), p01 = __expf(accS[ni][1] - mn0);
            float p10 = __expf(accS[ni][2] - mn1), p11 = __expf(accS[ni][3] - mn1);
            ps0 += p00 + p01; ps1 += p10 + p11;
            unsigned col2 = (unsigned)(warp_n * 32 + ni * 8 + 2 * t) * 2u;
            *(__nv_bfloat162*)(smem + FA_SP + swz((unsigned)r0 * 128u + col2)) = __floats2bfloat162_rn(p00, p01);
            *(__nv_bfloat162*)(smem + FA_SP + swz((unsigned)r1 * 128u + col2)) = __floats2bfloat162_rn(p10, p11);
        }
        ps0 += __shfl_xor_sync(~0u, ps0, 1); ps0 += __shfl_xor_sync(~0u, ps0, 2);
        ps1 += __shfl_xor_sync(~0u, ps1, 1); ps1 += __shfl_xor_sync(~0u, ps1, 2);
        if (t == 0) { fRS[warp_n * 128 + r0] = ps0; fRS[warp_n * 128 + r1] = ps1; }
        #pragma unroll
        for (int ni = 0; ni < 16; ni++) {
            accO[ni][0] *= al0; accO[ni][1] *= al0;
            accO[ni][2] *= al1; accO[ni][3] *= al1;
        }
        PAIR_BAR();
        if (warp_n == 0 && t == 0) {
            fSM[r0] = mn0;
            fSL[r0] = fSL[r0] * al0 + fRS[r0] + fRS[128 + r0];
            fSM[r1] = mn1;
            fSL[r1] = fSL[r1] * al1 + fRS[r1] + fRS[128 + r1];
        }
        unsigned vbase = sb + FA_SV + buf * 32768u;
        #pragma unroll
        for (int kst = 0; kst < 4; kst++) {
            unsigned kc = kst * 32u;
            unsigned af[4];
            LDMX4(af, sb + FA_SP + swz((warp_m * 16 + arow_l) * 128u + kc + acol));
            #pragma unroll
            for (int pi = 0; pi < 8; pi++) {
                unsigned bf[4];
                LDMX4(bf, vbase + swz((warp_n * 128 + pi * 16 + brow_l) * 128u + kc + bcol));
                MMAB(accO[2*pi],   af, bf[0], bf[1]);
                MMAB(accO[2*pi+1], af, bf[2], bf[3]);
            }
        }
        __syncthreads();
        int jn = (it + 2) * 64;
        if (jn < 4096) { FA_KV(buf, jn); }
        asm volatile("cp.async.commit_group;");
    }
    float il0 = 1.f / fSL[r0], il1 = 1.f / fSL[r1];
    __nv_bfloat16* o0 = ao + (size_t)b * CHW + (size_t)(q0 + r0) * 256;
    __nv_bfloat16* o1 = ao + (size_t)b * CHW + (size_t)(q0 + r1) * 256;
    #pragma unroll
    for (int ni = 0; ni < 16; ni++) {
        int dcol = warp_n * 128 + ni * 8 + 2 * t;
        *(__nv_bfloat162*)(o0 + dcol) = __floats2bfloat162_rn(accO[ni][0] * il0, accO[ni][1] * il0);
        *(__nv_bfloat162*)(o1 + dcol) = __floats2bfloat162_rn(accO[ni][2] * il1, accO[ni][3] * il1);
    }
}

// V transpose bf16; grid (128, 8, BB), block (32,8)
__global__ void trb_kernel(const __nv_bfloat16* __restrict__ in, __nv_bfloat16* __restrict__ out) {
    __shared__ unsigned short t[32][33];
    int i0 = blockIdx.x * 32, j0 = blockIdx.y * 32, b = blockIdx.z;
    int tx = threadIdx.x, ty = threadIdx.y;
    const unsigned short* ip = (const unsigned short*)(in + (size_t)b * 3 * CHW);
    unsigned short* op = (unsigned short*)(out + (size_t)b * CHW);
    #pragma unroll
    for (int r = 0; r < 4; r++)
        t[ty + r*8][tx] = ip[(size_t)(i0 + ty + r*8) * 768 + 512 + j0 + tx];
    __syncthreads();
    #pragma unroll
    for (int r = 0; r < 4; r++)
        op[(size_t)(j0 + ty + r*8) * 4096 + i0 + tx] = t[tx][ty + r*8];
}

// ====== GroupNorm partial stats: grid BB*32*4, block 256; part[blk]=(sum, sq) ======
template<int NCHW>
__global__ void gn_part(const float* __restrict__ x, float* __restrict__ part) {
    __shared__ float rsh[256], rqh[256];
    int blk = blockIdx.x;
    int bg = blk >> 2, ck = blk & 3;
    int b = bg >> 5, grp = bg & 31;
    int tid = threadIdx.x;
    float sum = 0.f, sq = 0.f;
    if (NCHW) {
        const float4* x4 = (const float4*)(x + (size_t)b * CHW + (size_t)grp * 8 * 4096) + ck * 2048;
        for (int i = tid; i < 2048; i += 256) {
            float4 v = x4[i];
            sum += (v.x + v.y) + (v.z + v.w);
            sq += v.x*v.x + v.y*v.y + v.z*v.z + v.w*v.w;
        }
    } else {
        const float* xp = x + (size_t)b * CHW + grp * 8 + (size_t)ck * 1024 * 256;
        for (int i = tid; i < 1024; i += 256) {
            float4 v0 = *(const float4*)&xp[(size_t)i * 256];
            float4 v1 = *(const float4*)&xp[(size_t)i * 256 + 4];
            sum += (v0.x+v0.y)+(v0.z+v0.w)+(v1.x+v1.y)+(v1.z+v1.w);
            sq += v0.x*v0.x+v0.y*v0.y+v0.z*v0.z+v0.w*v0.w+v1.x*v1.x+v1.y*v1.y+v1.z*v1.z+v1.w*v1.w;
        }
    }
    rsh[tid] = sum; rqh[tid] = sq;
    __syncthreads();
    for (int st = 128; st > 0; st >>= 1) {
        if (tid < st) { rsh[tid] += rsh[tid+st]; rqh[tid] += rqh[tid+st]; }
        __syncthreads();
    }
    if (tid == 0) { part[blk * 2] = rsh[0]; part[blk * 2 + 1] = rqh[0]; }
}

__device__ __forceinline__ void gn_minv(const float* part, int bg, float& m, float& inv) {
    float s = (part[(bg*4)*2]   + part[(bg*4+1)*2])   + (part[(bg*4+2)*2]   + part[(bg*4+3)*2]);
    float q = (part[(bg*4)*2+1] + part[(bg*4+1)*2+1]) + (part[(bg*4+2)*2+1] + part[(bg*4+3)*2+1]);
    m = s * (1.f/32768.f);
    inv = rsqrtf(q * (1.f/32768.f) - m*m + 1e-5f);
}

// ====== GroupNorm apply from NCHW -> NHWC tf32 f32 (+SiLU); grid BB*32*4, block 256 ======
__global__ void gn_apply_nchw(const float* __restrict__ x, const float* __restrict__ sc,
                              const float* __restrict__ bi, const float* __restrict__ part,
                              float* __restrict__ y) {
    int bg = blockIdx.x >> 2, ck = blockIdx.x & 3;
    int b = bg >> 5, grp = bg & 31;
    const float* xp = x + (size_t)b * CHW + (size_t)grp * 8 * 4096;
    float m, inv;
    gn_minv(part, bg, m, inv);
    float aa[8], bb[8];
    #pragma unroll
    for (int c = 0; c < 8; c++) { aa[c] = inv * sc[grp*8+c]; bb[c] = bi[grp*8+c] - m * aa[c]; }
    int p0 = ck * 1024;
    for (int p = p0 + threadIdx.x; p < p0 + 1024; p += 256) {
        float v[8];
        #pragma unroll
        for (int c = 0; c < 8; c++) {
            float tv = xp[(size_t)c * 4096 + p] * aa[c] + bb[c];
            tv = tv / (1.f + __expf(-tv));
            v[c] = rnd_tf32(tv);
        }
        float* yp = y + (size_t)b * CHW + (size_t)p * 256 + grp * 8;
        *(float4*)yp       = make_float4(v[0],v[1],v[2],v[3]);
        *(float4*)(yp + 4) = make_float4(v[4],v[5],v[6],v[7]);
    }
}

// ====== GroupNorm apply NHWC (+opt SiLU); OUT16=0 tf32 f32, OUT16=1 bf16; grid BB*32*4, block 256
template<int OUT16>
__global__ void gn_apply_nhwc(const float* __restrict__ x, const float* __restrict__ sc,
                              const float* __restrict__ bi, const float* __restrict__ part,
                              void* __restrict__ yv, int dosilu) {
    int bg = blockIdx.x >> 2, ck = blockIdx.x & 3;
    int b = bg >> 5, grp = bg & 31;
    const float* xp = x + (size_t)b * CHW + grp * 8;
    float m, inv;
    gn_minv(part, bg, m, inv);
    float aa[8], bb[8];
    #pragma unroll
    for (int j = 0; j < 8; j++) { aa[j] = inv * sc[grp*8+j]; bb[j] = bi[grp*8+j] - m * aa[j]; }
    int p0 = ck * 1024;
    for (int i = p0 + threadIdx.x; i < p0 + 1024; i += 256) {
        float4 v0 = *(const float4*)&xp[(size_t)i * 256];
        float4 v1 = *(const float4*)&xp[(size_t)i * 256 + 4];
        float v[8] = { v0.x,v0.y,v0.z,v0.w,v1.x,v1.y,v1.z,v1.w };
        #pragma unroll
        for (int j = 0; j < 8; j++) {
            float tv = v[j]*aa[j] + bb[j];
            if (dosilu) tv = tv / (1.f + __expf(-tv));
            v[j] = tv;
        }
        if (OUT16) {
            __nv_bfloat16* yp = (__nv_bfloat16*)yv + (size_t)b * CHW + grp * 8 + (size_t)i * 256;
            __nv_bfloat162 o[4];
            #pragma unroll
            for (int j = 0; j < 4; j++) o[j] = __floats2bfloat162_rn(v[2*j], v[2*j+1]);
            *(uint4*)yp = *(uint4*)o;
        } else {
            float* yp = (float*)yv + (size_t)b * CHW + grp * 8 + (size_t)i * 256;
            #pragma unroll
            for (int j = 0; j < 8; j++) v[j] = rnd_tf32(v[j]);
            *(float4*)yp       = make_float4(v[0],v[1],v[2],v[3]);
            *(float4*)(yp + 4) = make_float4(v[4],v[5],v[6],v[7]);
        }
    }
}

// both conv weights; grid (9, 512), block 256
__global__ void wtrans2(const float* __restrict__ w1, const float* __restrict__ w2,
                        float* __restrict__ wt1, float* __restrict__ wt2) {
    int o = blockIdx.y;
    int ko = blockIdx.x * 256 + threadIdx.x;
    const float* w = (o < 256) ? w1 : w2;
    float* wt = (o < 256) ? wt1 : wt2;
    int oo = o & 255;
    wt[(size_t)oo * KC + ko] = rnd_tf32(w[(size_t)oo * KC + (ko & 255) * 9 + (ko >> 8)]);
}

// qkv_w + out_w -> bf16; grid 1024, block 256
__global__ void wcast_bf(const float* __restrict__ qw, const float* __restrict__ ow,
                         __nv_bfloat16* __restrict__ qwb, __nv_bfloat16* __restrict__ owb) {
    int i = blockIdx.x * 256 + threadIdx.x;
    if (i < 768 * 256) qwb[i] = __float2bfloat16(qw[i]);
    else owb[i - 768 * 256] = __float2bfloat16(ow[i - 768 * 256]);
}

// grid (BB, 4), block 128
__global__ void film_mlp(const float* __restrict__ te, const float* __restrict__ w,
                         const float* __restrict__ bi, float* __restrict__ gb) {
    __shared__ float s_te[256];
    int b = blockIdx.x, tid = threadIdx.x;
    for (int i = tid; i < 256; i += 128) {
        float v = te[b * 256 + i];
        s_te[i] = v / (1.f + __expf(-v));
    }
    __syncthreads();
    int j = blockIdx.y * 128 + tid;
    const float* wr = w + (size_t)j * 256;
    float acc = bi[j];
    for (int t = 0; t < 256; t++) acc += s_te[t] * wr[t];
    gb[b * 512 + j] = acc;
}

extern "C" void kernel_launch(void* const* d_in, const int* in_sizes, int n_in,
                              void* d_out, int out_size) {
    const float* x = (const float*)d_in[0];
    const float* te = (const float*)d_in[1];
    const float* gn1_s = (const float*)d_in[2];
    const float* gn1_b = (const float*)d_in[3];
    const float* conv1_w = (const float*)d_in[4];
    const float* conv1_b = (const float*)d_in[5];
    const float* mlp_w = (const float*)d_in[6];
    const float* mlp_b = (const float*)d_in[7];
    const float* gn2_s = (const float*)d_in[8];
    const float* gn2_b = (const float*)d_in[9];
    const float* conv2_w = (const float*)d_in[10];
    const float* conv2_b = (const float*)d_in[11];
    const float* gnA_s = (const float*)d_in[12];
    const float* gnA_b = (const float*)d_in[13];
    const float* qkv_w = (const float*)d_in[14];
    const float* out_w = (const float*)d_in[15];
    const float* out_b = (const float*)d_in[16];
    float* out = (float*)d_out;

    float *a,*h,*xr,*gb,*part,*w1t,*w2t;
    __nv_bfloat16 *ah,*qwb,*owb,*qkvb,*vtb,*aob;
    cudaGetSymbolAddress((void**)&a, g_a);    cudaGetSymbolAddress((void**)&h, g_h);
    cudaGetSymbolAddress((void**)&xr, g_xr);  cudaGetSymbolAddress((void**)&gb, g_gb);
    cudaGetSymbolAddress((void**)&part, g_part);
    cudaGetSymbolAddress((void**)&w1t, g_w1t);cudaGetSymbolAddress((void**)&w2t, g_w2t);
    cudaGetSymbolAddress((void**)&ah, g_ah);  cudaGetSymbolAddress((void**)&qwb, g_qwb);
    cudaGetSymbolAddress((void**)&owb, g_owb);cudaGetSymbolAddress((void**)&qkvb, g_qkvb);
    cudaGetSymbolAddress((void**)&vtb, g_vtb);cudaGetSymbolAddress((void**)&aob, g_aob);

    static int init_done = 0;
    static cudaStream_t s2;
    static cudaEvent_t ev0, ev1;
    if (!init_done) {
        cudaFuncSetAttribute(gemm_conv, cudaFuncAttributeMaxDynamicSharedMemorySize, 196608);
        cudaFuncSetAttribute(gemm_bf, cudaFuncAttributeMaxDynamicSharedMemorySize, 147456);
        cudaFuncSetAttribute(gemm_out, cudaFuncAttributeMaxDynamicSharedMemorySize, 147456);
        cudaFuncSetAttribute(flash_attn, cudaFuncAttributeMaxDynamicSharedMemorySize, FA_SMEM);
        cudaStreamCreate(&s2);
        cudaEventCreateWithFlags(&ev0, cudaEventDisableTiming);
        cudaEventCreateWithFlags(&ev1, cudaEventDisableTiming);
        init_done = 1;
    }
    const float* NUL = (const float*)0;
    dim3 tb(32, 8);

    // fork: setup kernels on side stream, overlapped with gn1
    cudaEventRecord(ev0, 0);
    cudaStreamWaitEvent(s2, ev0, 0);
    film_mlp<<<dim3(BB, 4), 128, 0, s2>>>(te, mlp_w, mlp_b, gb);
    wtrans2<<<dim3(9, 512), 256, 0, s2>>>(conv1_w, conv2_w, w1t, w2t);
    wcast_bf<<<1024, 256, 0, s2>>>(qkv_w, out_w, qwb, owb);
    cudaEventRecord(ev1, s2);

    // gn1: NCHW partial stats + apply
    gn_part<1><<<BB*32*4, 256>>>(x, part);
    gn_apply_nchw<<<BB*32*4, 256>>>(x, gn1_s, gn1_b, part, a);
    cudaStreamWaitEvent(0, ev1, 0);

    // conv1 (implicit im2col) + bias + FiLM
    gemm_conv<<<dim3(16, 2, BB), 256, 196608>>>(a, w1t, h, conv1_b, gb, NUL);

    // conv2 + bias + x residual (NCHW)
    gn_part<0><<<BB*32*4, 256>>>(h, part);
    gn_apply_nhwc<0><<<BB*32*4, 256>>>(h, gn2_s, gn2_b, part, a, 1);
    gemm_conv<<<dim3(16, 2, BB), 256, 196608>>>(a, w2t, xr, conv2_b, NUL, x);

    // attention (all bf16)
    gn_part<0><<<BB*32*4, 256>>>(xr, part);
    gn_apply_nhwc<1><<<BB*32*4, 256>>>(xr, gnA_s, gnA_b, part, ah, 0);
    gemm_bf<<<dim3(16, 6, BB), 256, 147456>>>(ah, 256, CHW, qwb, 256, qkvb, 768, 3*CHW, 256);
    trb_kernel<<<dim3(128, 8, BB), tb>>>(qkvb, vtb);
    flash_attn<<<dim3(32, BB), 512, FA_SMEM>>>(qkvb, vtb, aob);
    gemm_out<<<dim3(16, 2, BB), 256, 147456>>>(aob, owb, out, out_b, xr);
}

// round 16
// speedup vs baseline: 1.0045x; 1.0045x over previous
#include <cuda_runtime.h>
#include <cuda_bf16.h>
#include <math.h>

#define BB 4
#define CHW 1048576LL
#define KC 2304

__device__ float g_a  [BB*CHW];
__device__ float g_h  [BB*CHW];
__device__ float g_xr [BB*CHW];
__device__ float g_gb [BB*512];
__device__ float g_part[BB*32*4*2];
__device__ float g_w1t[256*KC];
__device__ float g_w2t[256*KC];
__device__ __nv_bfloat16 g_ah  [BB*CHW];
__device__ __nv_bfloat16 g_qwb [768*256];
__device__ __nv_bfloat16 g_owb [256*256];
__device__ __nv_bfloat16 g_qkvb[BB*3*CHW];
__device__ __nv_bfloat16 g_vtb [BB*CHW];
__device__ __nv_bfloat16 g_aob [BB*CHW];

__device__ __forceinline__ unsigned smem_u32(const void* p){
    unsigned r;
    asm("{ .reg .u64 t; cvta.to.shared.u64 t, %1; cvt.u32.u64 %0, t; }" : "=r"(r) : "l"(p));
    return r;
}
__device__ __forceinline__ float rnd_tf32(float f){
    unsigned r; asm("cvt.rna.tf32.f32 %0, %1;" : "=r"(r) : "f"(f));
    return __uint_as_float(r);
}
__device__ __forceinline__ unsigned swz(unsigned off){ return off ^ ((off >> 3) & 0x70u); }

#define LDMX4(r, addr) \
    asm volatile("ldmatrix.sync.aligned.m8n8.x4.shared.b16 {%0,%1,%2,%3}, [%4];" \
        : "=r"((r)[0]),"=r"((r)[1]),"=r"((r)[2]),"=r"((r)[3]) : "r"(addr))
#define MMAT(c, a, b0, b1) \
    asm volatile("mma.sync.aligned.m16n8k8.row.col.f32.tf32.tf32.f32 " \
        "{%0,%1,%2,%3},{%4,%5,%6,%7},{%8,%9},{%0,%1,%2,%3};" \
        : "+f"((c)[0]),"+f"((c)[1]),"+f"((c)[2]),"+f"((c)[3]) \
        : "r"((a)[0]),"r"((a)[1]),"r"((a)[2]),"r"((a)[3]),"r"(b0),"r"(b1))
#define MMAB(c, a, b0, b1) \
    asm volatile("mma.sync.aligned.m16n8k16.row.col.f32.bf16.bf16.f32 " \
        "{%0,%1,%2,%3},{%4,%5,%6,%7},{%8,%9},{%0,%1,%2,%3};" \
        : "+f"((c)[0]),"+f"((c)[1]),"+f"((c)[2]),"+f"((c)[3]) \
        : "r"((a)[0]),"r"((a)[1]),"r"((a)[2]),"r"((a)[3]),"r"(b0),"r"(b1))

// ====== tf32 conv GEMM (implicit im2col), 256x128 tile, 4-stage; res in NCHW ======
__global__ void __launch_bounds__(256, 1) gemm_conv(
    const float* __restrict__ A, const float* __restrict__ B,
    float* __restrict__ Y,
    const float* __restrict__ bias, const float* __restrict__ filmB,
    const float* __restrict__ resN)
{
    extern __shared__ char smem[];
    unsigned sbase = smem_u32(smem);
    int tid = threadIdx.x, lane = tid & 31, wid = tid >> 5;
    int warp_m = wid & 3, warp_n = wid >> 2;
    int b = blockIdx.z;
    int m0 = blockIdx.x * 256, n0 = blockIdx.y * 128;
    const float* Ab = A + (size_t)b * CHW;
    const float* Bb = B + (size_t)n0 * KC;

    float acc[4][8][4];
    #pragma unroll
    for (int mi = 0; mi < 4; mi++)
        #pragma unroll
        for (int ni = 0; ni < 8; ni++)
            #pragma unroll
            for (int e = 0; e < 4; e++) acc[mi][ni][e] = 0.f;

#define ISSUE_C(st, kb) { \
    unsigned ab_ = sbase + (st) * 32768u; \
    unsigned bb_ = sbase + 131072u + (st) * 16384u; \
    int t_ = (kb) >> 3; int kh_ = t_ / 3 - 1; int kw_ = t_ - (t_ / 3) * 3 - 1; \
    int cb_ = ((kb) & 7) * 32; \
    _Pragma("unroll") \
    for (int i_ = 0; i_ < 8; i_++) { \
        int c_ = tid + i_ * 256; int row_ = c_ >> 3, seg_ = c_ & 7; \
        int p_ = m0 + row_; \
        int h2_ = (p_ >> 6) + kh_, w2_ = (p_ & 63) + kw_; \
        int ok_ = ((unsigned)h2_ < 64u) && ((unsigned)w2_ < 64u); \
        int hc_ = ok_ ? h2_ : 0, wc_ = ok_ ? w2_ : 0; \
        unsigned sz_ = ok_ ? 16u : 0u; \
        const float* src_ = Ab + (size_t)((hc_ << 6) + wc_) * 256 + cb_ + seg_ * 4; \
        unsigned d_ = ab_ + swz((unsigned)row_ * 128u + seg_ * 16u); \
        asm volatile("cp.async.cg.shared.global [%0], [%1], 16, %2;" :: "r"(d_), "l"(src_), "r"(sz_)); } \
    { const float* Bs_ = Bb + (kb) * 32; \
    _Pragma("unroll") \
    for (int i_ = 0; i_ < 4; i_++) { \
        int c_ = tid + i_ * 256; int row_ = c_ >> 3, seg_ = c_ & 7; \
        unsigned d_ = bb_ + swz((unsigned)row_ * 128u + seg_ * 16u); \
        asm volatile("cp.async.cg.shared.global [%0], [%1], 16;" :: "r"(d_), "l"(Bs_ + (size_t)row_ * KC + seg_ * 4)); } } \
    asm volatile("cp.async.commit_group;"); }

    const int nkb = KC >> 5;
    ISSUE_C(0, 0); ISSUE_C(1, 1); ISSUE_C(2, 2);

    unsigned arow = (unsigned)(warp_m * 64 + (lane & 7) + (lane & 8));
    unsigned acol = (lane & 16) ? 16u : 0u;
    unsigned brow = (unsigned)(warp_n * 64 + (lane & 7) + ((lane & 16) >> 1));
    unsigned bcol = (lane & 8) ? 16u : 0u;

    for (int kb = 0; kb < nkb; kb++) {
        int st = kb & 3;
        asm volatile("cp.async.wait_group 2;" ::: "memory");
        __syncthreads();
        unsigned ab_ = sbase + st * 32768u;
        unsigned bb_ = sbase + 131072u + st * 16384u;
        #pragma unroll
        for (int k8 = 0; k8 < 4; k8++) {
            unsigned kc = k8 * 32u;
            unsigned af[4][4], bf[4][4];
            #pragma unroll
            for (int mi = 0; mi < 4; mi++)
                LDMX4(af[mi], ab_ + swz((arow + mi * 16u) * 128u + kc + acol));
            #pragma unroll
            for (int pi = 0; pi < 4; pi++)
                LDMX4(bf[pi], bb_ + swz((brow + pi * 16u) * 128u + kc + bcol));
            #pragma unroll
            for (int mi = 0; mi < 4; mi++)
                #pragma unroll
                for (int pi = 0; pi < 4; pi++) {
                    MMAT(acc[mi][2*pi],   af[mi], bf[pi][0], bf[pi][1]);
                    MMAT(acc[mi][2*pi+1], af[mi], bf[pi][2], bf[pi][3]);
                }
        }
        __syncthreads();
        if (kb + 3 < nkb) { ISSUE_C((kb + 3) & 3, kb + 3); }
        else asm volatile("cp.async.commit_group;");
    }

    const float* fg = filmB ? (filmB + (size_t)b * 512) : (const float*)0;
    const float* Rb = resN ? (resN + (size_t)b * CHW) : (const float*)0;
    int g = lane >> 2, t = lane & 3;
    #pragma unroll
    for (int mi = 0; mi < 4; mi++) {
        #pragma unroll
        for (int r = 0; r < 2; r++) {
            int m = m0 + warp_m * 64 + mi * 16 + g + r * 8;
            float* Yr = Y + (size_t)b * CHW + (size_t)m * 256;
            #pragma unroll
            for (int ni = 0; ni < 8; ni++) {
                int n = n0 + warp_n * 64 + ni * 8 + 2 * t;
                float v0 = acc[mi][ni][2*r]     + bias[n];
                float v1 = acc[mi][ni][2*r + 1] + bias[n + 1];
                if (fg) {
                    v0 = (1.f + fg[n]) * v0 + fg[256 + n];
                    v1 = (1.f + fg[n + 1]) * v1 + fg[256 + n + 1];
                }
                if (Rb) {
                    v0 += Rb[(size_t)n * 4096 + m];
                    v1 += Rb[(size_t)(n + 1) * 4096 + m];
                }
                *(float2*)&Yr[n] = make_float2(v0, v1);
            }
        }
    }
}

// ====== bf16 GEMM (qkv proj) with fused V transpose; grid (16, 6, BB) ======
// n0 < 512: write qkvb[t][768-row]; n0 >= 512: staged transpose into vtb[d][t]
__global__ void __launch_bounds__(256, 1) gemm_bf(
    const __nv_bfloat16* __restrict__ A, int lda, long long sA,
    const __nv_bfloat16* __restrict__ B, int ldb,
    __nv_bfloat16* __restrict__ Yb, int ldy, long long sY, int K,
    __nv_bfloat16* __restrict__ Vt)
{
    extern __shared__ char smem[];
    unsigned sbase = smem_u32(smem);
    int tid = threadIdx.x, lane = tid & 31, wid = tid >> 5;
    int warp_m = wid & 3, warp_n = wid >> 2;
    int b = blockIdx.z;
    int m0 = blockIdx.x * 256, n0 = blockIdx.y * 128;
    const __nv_bfloat16* Ab = A + sA * b + (size_t)m0 * lda;
    const __nv_bfloat16* Bb = B + (size_t)n0 * ldb;

    float acc[4][8][4];
    #pragma unroll
    for (int mi = 0; mi < 4; mi++)
        #pragma unroll
        for (int ni = 0; ni < 8; ni++)
            #pragma unroll
            for (int e = 0; e < 4; e++) acc[mi][ni][e] = 0.f;

#define ISSUE_B(st, kb) { \
    unsigned ab_ = sbase + (st) * 32768u; \
    unsigned bb_ = sbase + 98304u + (st) * 16384u; \
    const __nv_bfloat16* As_ = Ab + (kb) * 64; \
    const __nv_bfloat16* Bs_ = Bb + (kb) * 64; \
    _Pragma("unroll") \
    for (int i_ = 0; i_ < 8; i_++) { \
        int c_ = tid + i_ * 256; int row_ = c_ >> 3, seg_ = c_ & 7; \
        unsigned d_ = ab_ + swz((unsigned)row_ * 128u + seg_ * 16u); \
        asm volatile("cp.async.cg.shared.global [%0], [%1], 16;" :: "r"(d_), "l"(As_ + (size_t)row_ * lda + seg_ * 8)); } \
    _Pragma("unroll") \
    for (int i_ = 0; i_ < 4; i_++) { \
        int c_ = tid + i_ * 256; int row_ = c_ >> 3, seg_ = c_ & 7; \
        unsigned d_ = bb_ + swz((unsigned)row_ * 128u + seg_ * 16u); \
        asm volatile("cp.async.cg.shared.global [%0], [%1], 16;" :: "r"(d_), "l"(Bs_ + (size_t)row_ * ldb + seg_ * 8)); } \
    asm volatile("cp.async.commit_group;"); }

    int nkb = K >> 6;
    ISSUE_B(0, 0);
    ISSUE_B(1, 1);

    unsigned arow = (unsigned)(warp_m * 64 + (lane & 7) + (lane & 8));
    unsigned acol = (lane & 16) ? 16u : 0u;
    unsigned brow = (unsigned)(warp_n * 64 + (lane & 7) + ((lane & 16) >> 1));
    unsigned bcol = (lane & 8) ? 16u : 0u;

    for (int kb = 0; kb < nkb; kb++) {
        int st = kb % 3;
        asm volatile("cp.async.wait_group 1;" ::: "memory");
        __syncthreads();
        unsigned ab_ = sbase + st * 32768u;
        unsigned bb_ = sbase + 98304u + st * 16384u;
        #pragma unroll
        for (int k16 = 0; k16 < 4; k16++) {
            unsigned kc = k16 * 32u;
            unsigned af[4][4], bf[4][4];
            #pragma unroll
            for (int mi = 0; mi < 4; mi++)
                LDMX4(af[mi], ab_ + swz((arow + mi * 16u) * 128u + kc + acol));
            #pragma unroll
            for (int pi = 0; pi < 4; pi++)
                LDMX4(bf[pi], bb_ + swz((brow + pi * 16u) * 128u + kc + bcol));
            #pragma unroll
            for (int mi = 0; mi < 4; mi++)
                #pragma unroll
                for (int pi = 0; pi < 4; pi++) {
                    MMAB(acc[mi][2*pi],   af[mi], bf[pi][0], bf[pi][1]);
                    MMAB(acc[mi][2*pi+1], af[mi], bf[pi][2], bf[pi][3]);
                }
        }
        __syncthreads();
        if (kb + 2 < nkb) { ISSUE_B((kb + 2) % 3, kb + 2); }
        else asm volatile("cp.async.commit_group;");
    }

    int g = lane >> 2, t = lane & 3;
    if (n0 < 512) {
        // Q/K halves: normal [t][768] bf16 write
        #pragma unroll
        for (int mi = 0; mi < 4; mi++) {
            #pragma unroll
            for (int r = 0; r < 2; r++) {
                int m = m0 + warp_m * 64 + mi * 16 + g + r * 8;
                #pragma unroll
                for (int ni = 0; ni < 8; ni++) {
                    int n = n0 + warp_n * 64 + ni * 8 + 2 * t;
                    __nv_bfloat16* Yp = Yb + sY * b + (size_t)m * ldy + n;
                    *(__nv_bfloat162*)Yp = __floats2bfloat162_rn(acc[mi][ni][2*r], acc[mi][ni][2*r+1]);
                }
            }
        }
    } else {
        // V half: staged transpose into vtb[d][t]
        __syncthreads();
        unsigned short* sw = (unsigned short*)smem + wid * (64 * 65);
        #pragma unroll
        for (int mi = 0; mi < 4; mi++) {
            #pragma unroll
            for (int r = 0; r < 2; r++) {
                int ml = mi * 16 + g + r * 8;
                #pragma unroll
                for (int ni = 0; ni < 8; ni++) {
                    int nl = ni * 8 + 2 * t;
                    __nv_bfloat162 p = __floats2bfloat162_rn(acc[mi][ni][2*r], acc[mi][ni][2*r+1]);
                    sw[ml * 65 + nl]     = ((unsigned short*)&p)[0];
                    sw[ml * 65 + nl + 1] = ((unsigned short*)&p)[1];
                }
            }
        }
        __syncwarp();
        int d_base = n0 - 512 + warp_n * 64;
        int t_base = m0 + warp_m * 64;
        unsigned short* Vb = (unsigned short*)(Vt + (size_t)b * CHW);
        for (int row = 0; row < 64; row++) {
            unsigned short w0 = sw[(lane * 2) * 65 + row];
            unsigned short w1 = sw[(lane * 2 + 1) * 65 + row];
            unsigned v = (unsigned)w0 | ((unsigned)w1 << 16);
            *(unsigned*)&Vb[(size_t)(d_base + row) * 4096 + t_base + lane * 2] = v;
        }
    }
}

// ====== bf16 out-projection GEMM, NCHW transposed epilogue; grid (16, 2, BB), K=256 ======
__global__ void __launch_bounds__(256, 1) gemm_out(
    const __nv_bfloat16* __restrict__ A,
    const __nv_bfloat16* __restrict__ B,
    float* __restrict__ Y,
    const float* __restrict__ bias, const float* __restrict__ res)
{
    extern __shared__ char smem[];
    unsigned sbase = smem_u32(smem);
    int tid = threadIdx.x, lane = tid & 31, wid = tid >> 5;
    int warp_m = wid & 3, warp_n = wid >> 2;
    int b = blockIdx.z;
    int m0 = blockIdx.x * 256, n0 = blockIdx.y * 128;
    const __nv_bfloat16* Ab = A + (size_t)b * CHW + (size_t)m0 * 256;
    const __nv_bfloat16* Bb = B + (size_t)n0 * 256;

    float acc[4][8][4];
    #pragma unroll
    for (int mi = 0; mi < 4; mi++)
        #pragma unroll
        for (int ni = 0; ni < 8; ni++)
            #pragma unroll
            for (int e = 0; e < 4; e++) acc[mi][ni][e] = 0.f;

#define ISSUE_O(st, kb) { \
    unsigned ab_ = sbase + (st) * 32768u; \
    unsigned bb_ = sbase + 98304u + (st) * 16384u; \
    const __nv_bfloat16* As_ = Ab + (kb) * 64; \
    const __nv_bfloat16* Bs_ = Bb + (kb) * 64; \
    _Pragma("unroll") \
    for (int i_ = 0; i_ < 8; i_++) { \
        int c_ = tid + i_ * 256; int row_ = c_ >> 3, seg_ = c_ & 7; \
        unsigned d_ = ab_ + swz((unsigned)row_ * 128u + seg_ * 16u); \
        asm volatile("cp.async.cg.shared.global [%0], [%1], 16;" :: "r"(d_), "l"(As_ + (size_t)row_ * 256 + seg_ * 8)); } \
    _Pragma("unroll") \
    for (int i_ = 0; i_ < 4; i_++) { \
        int c_ = tid + i_ * 256; int row_ = c_ >> 3, seg_ = c_ & 7; \
        unsigned d_ = bb_ + swz((unsigned)row_ * 128u + seg_ * 16u); \
        asm volatile("cp.async.cg.shared.global [%0], [%1], 16;" :: "r"(d_), "l"(Bs_ + (size_t)row_ * 256 + seg_ * 8)); } \
    asm volatile("cp.async.commit_group;"); }

    ISSUE_O(0, 0);
    ISSUE_O(1, 1);

    unsigned arow = (unsigned)(warp_m * 64 + (lane & 7) + (lane & 8));
    unsigned acol = (lane & 16) ? 16u : 0u;
    unsigned brow = (unsigned)(warp_n * 64 + (lane & 7) + ((lane & 16) >> 1));
    unsigned bcol = (lane & 8) ? 16u : 0u;

    for (int kb = 0; kb < 4; kb++) {
        int st = kb % 3;
        asm volatile("cp.async.wait_group 1;" ::: "memory");
        __syncthreads();
        unsigned ab_ = sbase + st * 32768u;
        unsigned bb_ = sbase + 98304u + st * 16384u;
        #pragma unroll
        for (int k16 = 0; k16 < 4; k16++) {
            unsigned kc = k16 * 32u;
            unsigned af[4][4], bf[4][4];
            #pragma unroll
            for (int mi = 0; mi < 4; mi++)
                LDMX4(af[mi], ab_ + swz((arow + mi * 16u) * 128u + kc + acol));
            #pragma unroll
            for (int pi = 0; pi < 4; pi++)
                LDMX4(bf[pi], bb_ + swz((brow + pi * 16u) * 128u + kc + bcol));
            #pragma unroll
            for (int mi = 0; mi < 4; mi++)
                #pragma unroll
                for (int pi = 0; pi < 4; pi++) {
                    MMAB(acc[mi][2*pi],   af[mi], bf[pi][0], bf[pi][1]);
                    MMAB(acc[mi][2*pi+1], af[mi], bf[pi][2], bf[pi][3]);
                }
        }
        __syncthreads();
        if (kb + 2 < 4) { ISSUE_O((kb + 2) % 3, kb + 2); }
        else asm volatile("cp.async.commit_group;");
    }

    __syncthreads();
    float* sw = (float*)smem + wid * (64 * 65);
    const float* Rb = res + (size_t)b * CHW;
    int g = lane >> 2, t = lane & 3;
    #pragma unroll
    for (int mi = 0; mi < 4; mi++) {
        #pragma unroll
        for (int r = 0; r < 2; r++) {
            int ml = mi * 16 + g + r * 8;
            int m = m0 + warp_m * 64 + ml;
            #pragma unroll
            for (int ni = 0; ni < 8; ni++) {
                int nl = ni * 8 + 2 * t;
                int n = n0 + warp_n * 64 + nl;
                sw[ml * 65 + nl]     = acc[mi][ni][2*r]     + bias[n]     + Rb[(size_t)m * 256 + n];
                sw[ml * 65 + nl + 1] = acc[mi][ni][2*r + 1] + bias[n + 1] + Rb[(size_t)m * 256 + n + 1];
            }
        }
    }
    __syncwarp();
    int m_base = m0 + warp_m * 64, n_base = n0 + warp_n * 64;
    float* Yb_ = Y + (size_t)b * CHW;
    for (int row = 0; row < 64; row++) {
        float2 w = make_float2(sw[(lane * 2) * 65 + row], sw[(lane * 2 + 1) * 65 + row]);
        *(float2*)&Yb_[(size_t)(n_base + row) * 4096 + m_base + lane * 2] = w;
    }
}

// ====== fused flash attention (bf16); grid (32, BB), block 512 ======
#define FA_SQ 0u
#define FA_SK 65536u
#define FA_SV 131072u
#define FA_SP 196608u
#define FA_SM 212992u
#define FA_SL 213504u
#define FA_RM 214016u
#define FA_RS 215040u
#define FA_SMEM 216064
__global__ void __launch_bounds__(512, 1) flash_attn(
    const __nv_bfloat16* __restrict__ qkv, const __nv_bfloat16* __restrict__ vt,
    __nv_bfloat16* __restrict__ ao)
{
    extern __shared__ char smem[];
    unsigned sb = smem_u32(smem);
    float* fSM = (float*)(smem + FA_SM);
    float* fSL = (float*)(smem + FA_SL);
    float* fRM = (float*)(smem + FA_RM);
    float* fRS = (float*)(smem + FA_RS);
    int tid = threadIdx.x, lane = tid & 31, wid = tid >> 5;
    int warp_m = wid & 7, warp_n = wid >> 3;
    int b = blockIdx.y, q0 = blockIdx.x * 128;
    const __nv_bfloat16* qb = qkv + (size_t)b * 3 * CHW;
    const __nv_bfloat16* kb = qb + 256;
    const __nv_bfloat16* vb = vt + (size_t)b * CHW;
    int g = lane >> 2, t = lane & 3;
    unsigned arow_l = (unsigned)((lane & 7) + (lane & 8));
    unsigned acol = (lane & 16) ? 16u : 0u;
    unsigned brow_l = (unsigned)((lane & 7) + ((lane & 16) >> 1));
    unsigned bcol = (lane & 8) ? 16u : 0u;

#define PAIR_BAR() asm volatile("bar.sync %0, 64;" :: "r"(1 + warp_m) : "memory")

#define FA_KV(bufv, jv) { \
    _Pragma("unroll") \
    for (int i_ = 0; i_ < 4; i_++) { \
        int idx = tid + i_ * 512; int ch = idx >> 9, row = (idx >> 3) & 63, seg = idx & 7; \
        unsigned d_ = sb + FA_SK + (bufv) * 32768u + ch * 8192u + swz((unsigned)row * 128u + seg * 16u); \
        const __nv_bfloat16* s_ = kb + (size_t)((jv) + row) * 768 + ch * 64 + seg * 8; \
        asm volatile("cp.async.cg.shared.global [%0], [%1], 16;" :: "r"(d_), "l"(s_)); } \
    _Pragma("unroll") \
    for (int i_ = 0; i_ < 4; i_++) { \
        int idx = tid + i_ * 512; int row = idx >> 3, seg = idx & 7; \
        unsigned d_ = sb + FA_SV + (bufv) * 32768u + swz((unsigned)row * 128u + seg * 16u); \
        const __nv_bfloat16* s_ = vb + (size_t)row * 4096 + (jv) + seg * 8; \
        asm volatile("cp.async.cg.shared.global [%0], [%1], 16;" :: "r"(d_), "l"(s_)); } }

    #pragma unroll
    for (int i_ = 0; i_ < 8; i_++) {
        int idx = tid + i_ * 512; int ch = idx >> 10, row = (idx >> 3) & 127, seg = idx & 7;
        unsigned d_ = sb + FA_SQ + ch * 16384u + swz((unsigned)row * 128u + seg * 16u);
        const __nv_bfloat16* s_ = qb + (size_t)(q0 + row) * 768 + ch * 64 + seg * 8;
        asm volatile("cp.async.cg.shared.global [%0], [%1], 16;" :: "r"(d_), "l"(s_));
    }
    FA_KV(0, 0);
    asm volatile("cp.async.commit_group;");
    FA_KV(1, 64);
    asm volatile("cp.async.commit_group;");
    if (tid < 128) { fSM[tid] = -1e30f; fSL[tid] = 0.f; }

    float accO[16][4];
    #pragma unroll
    for (int ni = 0; ni < 16; ni++)
        #pragma unroll
        for (int e = 0; e < 4; e++) accO[ni][e] = 0.f;

    int r0 = warp_m * 16 + g, r1 = r0 + 8;

    for (int it = 0; it < 64; it++) {
        int buf = it & 1;
        asm volatile("cp.async.wait_group 1;" ::: "memory");
        __syncthreads();
        float accS[4][4];
        #pragma unroll
        for (int ni = 0; ni < 4; ni++)
            #pragma unroll
            for (int e = 0; e < 4; e++) accS[ni][e] = 0.f;
        unsigned kbase = sb + FA_SK + buf * 32768u;
        #pragma unroll
        for (int kst = 0; kst < 16; kst++) {
            unsigned ch = kst >> 2, kc = (kst & 3) * 32u;
            unsigned af[4], bf0[4], bf1[4];
            LDMX4(af, sb + FA_SQ + ch * 16384u + swz((warp_m * 16 + arow_l) * 128u + kc + acol));
            LDMX4(bf0, kbase + ch * 8192u + swz((warp_n * 32 + brow_l) * 128u + kc + bcol));
            LDMX4(bf1, kbase + ch * 8192u + swz((warp_n * 32 + 16 + brow_l) * 128u + kc + bcol));
            MMAB(accS[0], af, bf0[0], bf0[1]); MMAB(accS[1], af, bf0[2], bf0[3]);
            MMAB(accS[2], af, bf1[0], bf1[1]); MMAB(accS[3], af, bf1[2], bf1[3]);
        }
        #pragma unroll
        for (int ni = 0; ni < 4; ni++)
            #pragma unroll
            for (int e = 0; e < 4; e++) accS[ni][e] *= 0.0625f;
        float pm0 = -1e30f, pm1 = -1e30f;
        #pragma unroll
        for (int ni = 0; ni < 4; ni++) {
            pm0 = fmaxf(pm0, fmaxf(accS[ni][0], accS[ni][1]));
            pm1 = fmaxf(pm1, fmaxf(accS[ni][2], accS[ni][3]));
        }
        pm0 = fmaxf(pm0, __shfl_xor_sync(~0u, pm0, 1)); pm0 = fmaxf(pm0, __shfl_xor_sync(~0u, pm0, 2));
        pm1 = fmaxf(pm1, __shfl_xor_sync(~0u, pm1, 1)); pm1 = fmaxf(pm1, __shfl_xor_sync(~0u, pm1, 2));
        if (t == 0) { fRM[warp_n * 128 + r0] = pm0; fRM[warp_n * 128 + r1] = pm1; }
        PAIR_BAR();
        float mo0 = fSM[r0], mo1 = fSM[r1];
        float mn0 = fmaxf(mo0, fmaxf(fRM[r0], fRM[128 + r0]));
        float mn1 = fmaxf(mo1, fmaxf(fRM[r1], fRM[128 + r1]));
        float al0 = __expf(mo0 - mn0), al1 = __expf(mo1 - mn1);
        float ps0 = 0.f, ps1 = 0.f;
        #pragma unroll
        for (int ni = 0; ni < 4; ni++) {
            float p00 = __expf(accS[ni][0] - mn0), p01 = __expf(accS[ni][1] - mn0);
            float p10 = __expf(accS[ni][2] - mn1), p11 = __expf(accS[ni][3] - mn1);
            ps0 += p00 + p01; ps1 += p10 + p11;
            unsigned col2 = (unsigned)(warp_n * 32 + ni * 8 + 2 * t) * 2u;
            *(__nv_bfloat162*)(smem + FA_SP + swz((unsigned)r0 * 128u + col2)) = __floats2bfloat162_rn(p00, p01);
            *(__nv_bfloat162*)(smem + FA_SP + swz((unsigned)r1 * 128u + col2)) = __floats2bfloat162_rn(p10, p11);
        }
        ps0 += __shfl_xor_sync(~0u, ps0, 1); ps0 += __shfl_xor_sync(~0u, ps0, 2);
        ps1 += __shfl_xor_sync(~0u, ps1, 1); ps1 += __shfl_xor_sync(~0u, ps1, 2);
        if (t == 0) { fRS[warp_n * 128 + r0] = ps0; fRS[warp_n * 128 + r1] = ps1; }
        #pragma unroll
        for (int ni = 0; ni < 16; ni++) {
            accO[ni][0] *= al0; accO[ni][1] *= al0;
            accO[ni][2] *= al1; accO[ni][3] *= al1;
        }
        PAIR_BAR();
        if (warp_n == 0 && t == 0) {
            fSM[r0] = mn0;
            fSL[r0] = fSL[r0] * al0 + fRS[r0] + fRS[128 + r0];
            fSM[r1] = mn1;
            fSL[r1] = fSL[r1] * al1 + fRS[r1] + fRS[128 + r1];
        }
        unsigned vbase = sb + FA_SV + buf * 32768u;
        #pragma unroll
        for (int kst = 0; kst < 4; kst++) {
            unsigned kc = kst * 32u;
            unsigned af[4];
            LDMX4(af, sb + FA_SP + swz((warp_m * 16 + arow_l) * 128u + kc + acol));
            #pragma unroll
            for (int pi = 0; pi < 8; pi++) {
                unsigned bf[4];
                LDMX4(bf, vbase + swz((warp_n * 128 + pi * 16 + brow_l) * 128u + kc + bcol));
                MMAB(accO[2*pi],   af, bf[0], bf[1]);
                MMAB(accO[2*pi+1], af, bf[2], bf[3]);
            }
        }
        __syncthreads();
        int jn = (it + 2) * 64;
        if (jn < 4096) { FA_KV(buf, jn); }
        asm volatile("cp.async.commit_group;");
    }
    float il0 = 1.f / fSL[r0], il1 = 1.f / fSL[r1];
    __nv_bfloat16* o0 = ao + (size_t)b * CHW + (size_t)(q0 + r0) * 256;
    __nv_bfloat16* o1 = ao + (size_t)b * CHW + (size_t)(q0 + r1) * 256;
    #pragma unroll
    for (int ni = 0; ni < 16; ni++) {
        int dcol = warp_n * 128 + ni * 8 + 2 * t;
        *(__nv_bfloat162*)(o0 + dcol) = __floats2bfloat162_rn(accO[ni][0] * il0, accO[ni][1] * il0);
        *(__nv_bfloat162*)(o1 + dcol) = __floats2bfloat162_rn(accO[ni][2] * il1, accO[ni][3] * il1);
    }
}

// ====== GroupNorm partial stats: grid BB*32*4, block 256; part[blk]=(sum, sq) ======
template<int NCHW>
__global__ void gn_part(const float* __restrict__ x, float* __restrict__ part) {
    __shared__ float rsh[256], rqh[256];
    int blk = blockIdx.x;
    int bg = blk >> 2, ck = blk & 3;
    int b = bg >> 5, grp = bg & 31;
    int tid = threadIdx.x;
    float sum = 0.f, sq = 0.f;
    if (NCHW) {
        const float4* x4 = (const float4*)(x + (size_t)b * CHW + (size_t)grp * 8 * 4096) + ck * 2048;
        for (int i = tid; i < 2048; i += 256) {
            float4 v = x4[i];
            sum += (v.x + v.y) + (v.z + v.w);
            sq += v.x*v.x + v.y*v.y + v.z*v.z + v.w*v.w;
        }
    } else {
        const float* xp = x + (size_t)b * CHW + grp * 8 + (size_t)ck * 1024 * 256;
        for (int i = tid; i < 1024; i += 256) {
            float4 v0 = *(const float4*)&xp[(size_t)i * 256];
            float4 v1 = *(const float4*)&xp[(size_t)i * 256 + 4];
            sum += (v0.x+v0.y)+(v0.z+v0.w)+(v1.x+v1.y)+(v1.z+v1.w);
            sq += v0.x*v0.x+v0.y*v0.y+v0.z*v0.z+v0.w*v0.w+v1.x*v1.x+v1.y*v1.y+v1.z*v1.z+v1.w*v1.w;
        }
    }
    rsh[tid] = sum; rqh[tid] = sq;
    __syncthreads();
    for (int st = 128; st > 0; st >>= 1) {
        if (tid < st) { rsh[tid] += rsh[tid+st]; rqh[tid] += rqh[tid+st]; }
        __syncthreads();
    }
    if (tid == 0) { part[blk * 2] = rsh[0]; part[blk * 2 + 1] = rqh[0]; }
}

__device__ __forceinline__ void gn_minv(const float* part, int bg, float& m, float& inv) {
    float s = (part[(bg*4)*2]   + part[(bg*4+1)*2])   + (part[(bg*4+2)*2]   + part[(bg*4+3)*2]);
    float q = (part[(bg*4)*2+1] + part[(bg*4+1)*2+1]) + (part[(bg*4+2)*2+1] + part[(bg*4+3)*2+1]);
    m = s * (1.f/32768.f);
    inv = rsqrtf(q * (1.f/32768.f) - m*m + 1e-5f);
}

// ====== GroupNorm apply from NCHW -> NHWC tf32 f32 (+SiLU); grid BB*32*4, block 256 ======
__global__ void gn_apply_nchw(const float* __restrict__ x, const float* __restrict__ sc,
                              const float* __restrict__ bi, const float* __restrict__ part,
                              float* __restrict__ y) {
    int bg = blockIdx.x >> 2, ck = blockIdx.x & 3;
    int b = bg >> 5, grp = bg & 31;
    const float* xp = x + (size_t)b * CHW + (size_t)grp * 8 * 4096;
    float m, inv;
    gn_minv(part, bg, m, inv);
    float aa[8], bb[8];
    #pragma unroll
    for (int c = 0; c < 8; c++) { aa[c] = inv * sc[grp*8+c]; bb[c] = bi[grp*8+c] - m * aa[c]; }
    int p0 = ck * 1024;
    for (int p = p0 + threadIdx.x; p < p0 + 1024; p += 256) {
        float v[8];
        #pragma unroll
        for (int c = 0; c < 8; c++) {
            float tv = xp[(size_t)c * 4096 + p] * aa[c] + bb[c];
            tv = tv / (1.f + __expf(-tv));
            v[c] = rnd_tf32(tv);
        }
        float* yp = y + (size_t)b * CHW + (size_t)p * 256 + grp * 8;
        *(float4*)yp       = make_float4(v[0],v[1],v[2],v[3]);
        *(float4*)(yp + 4) = make_float4(v[4],v[5],v[6],v[7]);
    }
}

// ====== GroupNorm apply NHWC (+opt SiLU); OUT16=0 tf32 f32, OUT16=1 bf16; grid BB*32*4, block 256
template<int OUT16>
__global__ void gn_apply_nhwc(const float* __restrict__ x, const float* __restrict__ sc,
                              const float* __restrict__ bi, const float* __restrict__ part,
                              void* __restrict__ yv, int dosilu) {
    int bg = blockIdx.x >> 2, ck = blockIdx.x & 3;
    int b = bg >> 5, grp = bg & 31;
    const float* xp = x + (size_t)b * CHW + grp * 8;
    float m, inv;
    gn_minv(part, bg, m, inv);
    float aa[8], bb[8];
    #pragma unroll
    for (int j = 0; j < 8; j++) { aa[j] = inv * sc[grp*8+j]; bb[j] = bi[grp*8+j] - m * aa[j]; }
    int p0 = ck * 1024;
    for (int i = p0 + threadIdx.x; i < p0 + 1024; i += 256) {
        float4 v0 = *(const float4*)&xp[(size_t)i * 256];
        float4 v1 = *(const float4*)&xp[(size_t)i * 256 + 4];
        float v[8] = { v0.x,v0.y,v0.z,v0.w,v1.x,v1.y,v1.z,v1.w };
        #pragma unroll
        for (int j = 0; j < 8; j++) {
            float tv = v[j]*aa[j] + bb[j];
            if (dosilu) tv = tv / (1.f + __expf(-tv));
            v[j] = tv;
        }
        if (OUT16) {
            __nv_bfloat16* yp = (__nv_bfloat16*)yv + (size_t)b * CHW + grp * 8 + (size_t)i * 256;
            __nv_bfloat162 o[4];
            #pragma unroll
            for (int j = 0; j < 4; j++) o[j] = __floats2bfloat162_rn(v[2*j], v[2*j+1]);
            *(uint4*)yp = *(uint4*)o;
        } else {
            float* yp = (float*)yv + (size_t)b * CHW + grp * 8 + (size_t)i * 256;
            #pragma unroll
            for (int j = 0; j < 8; j++) v[j] = rnd_tf32(v[j]);
            *(float4*)yp       = make_float4(v[0],v[1],v[2],v[3]);
            *(float4*)(yp + 4) = make_float4(v[4],v[5],v[6],v[7]);
        }
    }
}

// both conv weights; grid (9, 512), block 256
__global__ void wtrans2(const float* __restrict__ w1, const float* __restrict__ w2,
                        float* __restrict__ wt1, float* __restrict__ wt2) {
    int o = blockIdx.y;
    int ko = blockIdx.x * 256 + threadIdx.x;
    const float* w = (o < 256) ? w1 : w2;
    float* wt = (o < 256) ? wt1 : wt2;
    int oo = o & 255;
    wt[(size_t)oo * KC + ko] = rnd_tf32(w[(size_t)oo * KC + (ko & 255) * 9 + (ko >> 8)]);
}

// qkv_w + out_w -> bf16; grid 1024, block 256
__global__ void wcast_bf(const float* __restrict__ qw, const float* __restrict__ ow,
                         __nv_bfloat16* __restrict__ qwb, __nv_bfloat16* __restrict__ owb) {
    int i = blockIdx.x * 256 + threadIdx.x;
    if (i < 768 * 256) qwb[i] = __float2bfloat16(qw[i]);
    else owb[i - 768 * 256] = __float2bfloat16(ow[i - 768 * 256]);
}

// grid (BB, 4), block 128
__global__ void film_mlp(const float* __restrict__ te, const float* __restrict__ w,
                         const float* __restrict__ bi, float* __restrict__ gb) {
    __shared__ float s_te[256];
    int b = blockIdx.x, tid = threadIdx.x;
    for (int i = tid; i < 256; i += 128) {
        float v = te[b * 256 + i];
        s_te[i] = v / (1.f + __expf(-v));
    }
    __syncthreads();
    int j = blockIdx.y * 128 + tid;
    const float* wr = w + (size_t)j * 256;
    float acc = bi[j];
    for (int t = 0; t < 256; t++) acc += s_te[t] * wr[t];
    gb[b * 512 + j] = acc;
}

extern "C" void kernel_launch(void* const* d_in, const int* in_sizes, int n_in,
                              void* d_out, int out_size) {
    const float* x = (const float*)d_in[0];
    const float* te = (const float*)d_in[1];
    const float* gn1_s = (const float*)d_in[2];
    const float* gn1_b = (const float*)d_in[3];
    const float* conv1_w = (const float*)d_in[4];
    const float* conv1_b = (const float*)d_in[5];
    const float* mlp_w = (const float*)d_in[6];
    const float* mlp_b = (const float*)d_in[7];
    const float* gn2_s = (const float*)d_in[8];
    const float* gn2_b = (const float*)d_in[9];
    const float* conv2_w = (const float*)d_in[10];
    const float* conv2_b = (const float*)d_in[11];
    const float* gnA_s = (const float*)d_in[12];
    const float* gnA_b = (const float*)d_in[13];
    const float* qkv_w = (const float*)d_in[14];
    const float* out_w = (const float*)d_in[15];
    const float* out_b = (const float*)d_in[16];
    float* out = (float*)d_out;

    float *a,*h,*xr,*gb,*part,*w1t,*w2t;
    __nv_bfloat16 *ah,*qwb,*owb,*qkvb,*vtb,*aob;
    cudaGetSymbolAddress((void**)&a, g_a);    cudaGetSymbolAddress((void**)&h, g_h);
    cudaGetSymbolAddress((void**)&xr, g_xr);  cudaGetSymbolAddress((void**)&gb, g_gb);
    cudaGetSymbolAddress((void**)&part, g_part);
    cudaGetSymbolAddress((void**)&w1t, g_w1t);cudaGetSymbolAddress((void**)&w2t, g_w2t);
    cudaGetSymbolAddress((void**)&ah, g_ah);  cudaGetSymbolAddress((void**)&qwb, g_qwb);
    cudaGetSymbolAddress((void**)&owb, g_owb);cudaGetSymbolAddress((void**)&qkvb, g_qkvb);
    cudaGetSymbolAddress((void**)&vtb, g_vtb);cudaGetSymbolAddress((void**)&aob, g_aob);

    static int init_done = 0;
    static cudaStream_t s2;
    static cudaEvent_t ev0, ev1;
    if (!init_done) {
        cudaFuncSetAttribute(gemm_conv, cudaFuncAttributeMaxDynamicSharedMemorySize, 196608);
        cudaFuncSetAttribute(gemm_bf, cudaFuncAttributeMaxDynamicSharedMemorySize, 147456);
        cudaFuncSetAttribute(gemm_out, cudaFuncAttributeMaxDynamicSharedMemorySize, 147456);
        cudaFuncSetAttribute(flash_attn, cudaFuncAttributeMaxDynamicSharedMemorySize, FA_SMEM);
        cudaStreamCreate(&s2);
        cudaEventCreateWithFlags(&ev0, cudaEventDisableTiming);
        cudaEventCreateWithFlags(&ev1, cudaEventDisableTiming);
        init_done = 1;
    }
    const float* NUL = (const float*)0;

    // fork: setup kernels on side stream, overlapped with gn1
    cudaEventRecord(ev0, 0);
    cudaStreamWaitEvent(s2, ev0, 0);
    film_mlp<<<dim3(BB, 4), 128, 0, s2>>>(te, mlp_w, mlp_b, gb);
    wtrans2<<<dim3(9, 512), 256, 0, s2>>>(conv1_w, conv2_w, w1t, w2t);
    wcast_bf<<<1024, 256, 0, s2>>>(qkv_w, out_w, qwb, owb);
    cudaEventRecord(ev1, s2);

    // gn1: NCHW partial stats + apply
    gn_part<1><<<BB*32*4, 256>>>(x, part);
    gn_apply_nchw<<<BB*32*4, 256>>>(x, gn1_s, gn1_b, part, a);
    cudaStreamWaitEvent(0, ev1, 0);

    // conv1 (implicit im2col) + bias + FiLM
    gemm_conv<<<dim3(16, 2, BB), 256, 196608>>>(a, w1t, h, conv1_b, gb, NUL);

    // conv2 + bias + x residual (NCHW)
    gn_part<0><<<BB*32*4, 256>>>(h, part);
    gn_apply_nhwc<0><<<BB*32*4, 256>>>(h, gn2_s, gn2_b, part, a, 1);
    gemm_conv<<<dim3(16, 2, BB), 256, 196608>>>(a, w2t, xr, conv2_b, NUL, x);

    // attention (all bf16); qkv GEMM writes Q/K to qkvb and V transposed into vtb
    gn_part<0><<<BB*32*4, 256>>>(xr, part);
    gn_apply_nhwc<1><<<BB*32*4, 256>>>(xr, gnA_s, gnA_b, part, ah, 0);
    gemm_bf<<<dim3(16, 6, BB), 256, 147456>>>(ah, 256, CHW, qwb, 256, qkvb, 768, 3*CHW, 256, vtb);
    flash_attn<<<dim3(32, BB), 512, FA_SMEM>>>(qkvb, vtb, aob);
    gemm_out<<<dim3(16, 2, BB), 256, 147456>>>(aob, owb, out, out_b, xr);
}

// round 17
// speedup vs baseline: 1.0252x; 1.0206x over previous
#include <cuda_runtime.h>
#include <cuda_bf16.h>
#include <math.h>

#define BB 4
#define CHW 1048576LL
#define KC 2304

__device__ float g_a  [BB*CHW];
__device__ float g_h  [BB*CHW];
__device__ float g_xr [BB*CHW];
__device__ float g_gb [BB*512];
__device__ float g_part[BB*32*4*2];
__device__ float g_w1t[256*KC];
__device__ float g_w2t[256*KC];
__device__ __nv_bfloat16 g_ah  [BB*CHW];
__device__ __nv_bfloat16 g_qwb [768*256];
__device__ __nv_bfloat16 g_owb [256*256];
__device__ __nv_bfloat16 g_qkvb[BB*3*CHW];
__device__ __nv_bfloat16 g_vtb [BB*CHW];
__device__ __nv_bfloat16 g_aob [BB*CHW];

__device__ __forceinline__ unsigned smem_u32(const void* p){
    unsigned r;
    asm("{ .reg .u64 t; cvta.to.shared.u64 t, %1; cvt.u32.u64 %0, t; }" : "=r"(r) : "l"(p));
    return r;
}
__device__ __forceinline__ float rnd_tf32(float f){
    unsigned r; asm("cvt.rna.tf32.f32 %0, %1;" : "=r"(r) : "f"(f));
    return __uint_as_float(r);
}
__device__ __forceinline__ unsigned swz(unsigned off){ return off ^ ((off >> 3) & 0x70u); }

#define LDMX4(r, addr) \
    asm volatile("ldmatrix.sync.aligned.m8n8.x4.shared.b16 {%0,%1,%2,%3}, [%4];" \
        : "=r"((r)[0]),"=r"((r)[1]),"=r"((r)[2]),"=r"((r)[3]) : "r"(addr))
#define MMAT(c, a, b0, b1) \
    asm volatile("mma.sync.aligned.m16n8k8.row.col.f32.tf32.tf32.f32 " \
        "{%0,%1,%2,%3},{%4,%5,%6,%7},{%8,%9},{%0,%1,%2,%3};" \
        : "+f"((c)[0]),"+f"((c)[1]),"+f"((c)[2]),"+f"((c)[3]) \
        : "r"((a)[0]),"r"((a)[1]),"r"((a)[2]),"r"((a)[3]),"r"(b0),"r"(b1))
#define MMAB(c, a, b0, b1) \
    asm volatile("mma.sync.aligned.m16n8k16.row.col.f32.bf16.bf16.f32 " \
        "{%0,%1,%2,%3},{%4,%5,%6,%7},{%8,%9},{%0,%1,%2,%3};" \
        : "+f"((c)[0]),"+f"((c)[1]),"+f"((c)[2]),"+f"((c)[3]) \
        : "r"((a)[0]),"r"((a)[1]),"r"((a)[2]),"r"((a)[3]),"r"(b0),"r"(b1))

// ====== tf32 conv GEMM (implicit im2col), 256x128 tile, 4-stage; res in NCHW ======
__global__ void __launch_bounds__(256, 1) gemm_conv(
    const float* __restrict__ A, const float* __restrict__ B,
    float* __restrict__ Y,
    const float* __restrict__ bias, const float* __restrict__ filmB,
    const float* __restrict__ resN)
{
    extern __shared__ char smem[];
    unsigned sbase = smem_u32(smem);
    int tid = threadIdx.x, lane = tid & 31, wid = tid >> 5;
    int warp_m = wid & 3, warp_n = wid >> 2;
    int b = blockIdx.z;
    int m0 = blockIdx.x * 256, n0 = blockIdx.y * 128;
    const float* Ab = A + (size_t)b * CHW;
    const float* Bb = B + (size_t)n0 * KC;

    float acc[4][8][4];
    #pragma unroll
    for (int mi = 0; mi < 4; mi++)
        #pragma unroll
        for (int ni = 0; ni < 8; ni++)
            #pragma unroll
            for (int e = 0; e < 4; e++) acc[mi][ni][e] = 0.f;

#define ISSUE_C(st, kb) { \
    unsigned ab_ = sbase + (st) * 32768u; \
    unsigned bb_ = sbase + 131072u + (st) * 16384u; \
    int t_ = (kb) >> 3; int kh_ = t_ / 3 - 1; int kw_ = t_ - (t_ / 3) * 3 - 1; \
    int cb_ = ((kb) & 7) * 32; \
    _Pragma("unroll") \
    for (int i_ = 0; i_ < 8; i_++) { \
        int c_ = tid + i_ * 256; int row_ = c_ >> 3, seg_ = c_ & 7; \
        int p_ = m0 + row_; \
        int h2_ = (p_ >> 6) + kh_, w2_ = (p_ & 63) + kw_; \
        int ok_ = ((unsigned)h2_ < 64u) && ((unsigned)w2_ < 64u); \
        int hc_ = ok_ ? h2_ : 0, wc_ = ok_ ? w2_ : 0; \
        unsigned sz_ = ok_ ? 16u : 0u; \
        const float* src_ = Ab + (size_t)((hc_ << 6) + wc_) * 256 + cb_ + seg_ * 4; \
        unsigned d_ = ab_ + swz((unsigned)row_ * 128u + seg_ * 16u); \
        asm volatile("cp.async.cg.shared.global [%0], [%1], 16, %2;" :: "r"(d_), "l"(src_), "r"(sz_)); } \
    { const float* Bs_ = Bb + (kb) * 32; \
    _Pragma("unroll") \
    for (int i_ = 0; i_ < 4; i_++) { \
        int c_ = tid + i_ * 256; int row_ = c_ >> 3, seg_ = c_ & 7; \
        unsigned d_ = bb_ + swz((unsigned)row_ * 128u + seg_ * 16u); \
        asm volatile("cp.async.cg.shared.global [%0], [%1], 16;" :: "r"(d_), "l"(Bs_ + (size_t)row_ * KC + seg_ * 4)); } } \
    asm volatile("cp.async.commit_group;"); }

    const int nkb = KC >> 5;
    ISSUE_C(0, 0); ISSUE_C(1, 1); ISSUE_C(2, 2);

    unsigned arow = (unsigned)(warp_m * 64 + (lane & 7) + (lane & 8));
    unsigned acol = (lane & 16) ? 16u : 0u;
    unsigned brow = (unsigned)(warp_n * 64 + (lane & 7) + ((lane & 16) >> 1));
    unsigned bcol = (lane & 8) ? 16u : 0u;

    for (int kb = 0; kb < nkb; kb++) {
        int st = kb & 3;
        asm volatile("cp.async.wait_group 2;" ::: "memory");
        __syncthreads();
        unsigned ab_ = sbase + st * 32768u;
        unsigned bb_ = sbase + 131072u + st * 16384u;
        #pragma unroll
        for (int k8 = 0; k8 < 4; k8++) {
            unsigned kc = k8 * 32u;
            unsigned af[4][4], bf[4][4];
            #pragma unroll
            for (int mi = 0; mi < 4; mi++)
                LDMX4(af[mi], ab_ + swz((arow + mi * 16u) * 128u + kc + acol));
            #pragma unroll
            for (int pi = 0; pi < 4; pi++)
                LDMX4(bf[pi], bb_ + swz((brow + pi * 16u) * 128u + kc + bcol));
            #pragma unroll
            for (int mi = 0; mi < 4; mi++)
                #pragma unroll
                for (int pi = 0; pi < 4; pi++) {
                    MMAT(acc[mi][2*pi],   af[mi], bf[pi][0], bf[pi][1]);
                    MMAT(acc[mi][2*pi+1], af[mi], bf[pi][2], bf[pi][3]);
                }
        }
        // NOTE: no barrier here — ISSUE targets stage (kb-1)&3, fully consumed
        // before this iteration's top __syncthreads.
        if (kb + 3 < nkb) { ISSUE_C((kb + 3) & 3, kb + 3); }
        else asm volatile("cp.async.commit_group;");
    }

    const float* fg = filmB ? (filmB + (size_t)b * 512) : (const float*)0;
    const float* Rb = resN ? (resN + (size_t)b * CHW) : (const float*)0;
    int g = lane >> 2, t = lane & 3;
    #pragma unroll
    for (int mi = 0; mi < 4; mi++) {
        #pragma unroll
        for (int r = 0; r < 2; r++) {
            int m = m0 + warp_m * 64 + mi * 16 + g + r * 8;
            float* Yr = Y + (size_t)b * CHW + (size_t)m * 256;
            #pragma unroll
            for (int ni = 0; ni < 8; ni++) {
                int n = n0 + warp_n * 64 + ni * 8 + 2 * t;
                float v0 = acc[mi][ni][2*r]     + bias[n];
                float v1 = acc[mi][ni][2*r + 1] + bias[n + 1];
                if (fg) {
                    v0 = (1.f + fg[n]) * v0 + fg[256 + n];
                    v1 = (1.f + fg[n + 1]) * v1 + fg[256 + n + 1];
                }
                if (Rb) {
                    v0 += Rb[(size_t)n * 4096 + m];
                    v1 += Rb[(size_t)(n + 1) * 4096 + m];
                }
                *(float2*)&Yr[n] = make_float2(v0, v1);
            }
        }
    }
}

// ====== bf16 GEMM (qkv proj) with fused V transpose; grid (16, 6, BB) ======
__global__ void __launch_bounds__(256, 1) gemm_bf(
    const __nv_bfloat16* __restrict__ A, int lda, long long sA,
    const __nv_bfloat16* __restrict__ B, int ldb,
    __nv_bfloat16* __restrict__ Yb, int ldy, long long sY, int K,
    __nv_bfloat16* __restrict__ Vt)
{
    extern __shared__ char smem[];
    unsigned sbase = smem_u32(smem);
    int tid = threadIdx.x, lane = tid & 31, wid = tid >> 5;
    int warp_m = wid & 3, warp_n = wid >> 2;
    int b = blockIdx.z;
    int m0 = blockIdx.x * 256, n0 = blockIdx.y * 128;
    const __nv_bfloat16* Ab = A + sA * b + (size_t)m0 * lda;
    const __nv_bfloat16* Bb = B + (size_t)n0 * ldb;

    float acc[4][8][4];
    #pragma unroll
    for (int mi = 0; mi < 4; mi++)
        #pragma unroll
        for (int ni = 0; ni < 8; ni++)
            #pragma unroll
            for (int e = 0; e < 4; e++) acc[mi][ni][e] = 0.f;

#define ISSUE_B(st, kb) { \
    unsigned ab_ = sbase + (st) * 32768u; \
    unsigned bb_ = sbase + 98304u + (st) * 16384u; \
    const __nv_bfloat16* As_ = Ab + (kb) * 64; \
    const __nv_bfloat16* Bs_ = Bb + (kb) * 64; \
    _Pragma("unroll") \
    for (int i_ = 0; i_ < 8; i_++) { \
        int c_ = tid + i_ * 256; int row_ = c_ >> 3, seg_ = c_ & 7; \
        unsigned d_ = ab_ + swz((unsigned)row_ * 128u + seg_ * 16u); \
        asm volatile("cp.async.cg.shared.global [%0], [%1], 16;" :: "r"(d_), "l"(As_ + (size_t)row_ * lda + seg_ * 8)); } \
    _Pragma("unroll") \
    for (int i_ = 0; i_ < 4; i_++) { \
        int c_ = tid + i_ * 256; int row_ = c_ >> 3, seg_ = c_ & 7; \
        unsigned d_ = bb_ + swz((unsigned)row_ * 128u + seg_ * 16u); \
        asm volatile("cp.async.cg.shared.global [%0], [%1], 16;" :: "r"(d_), "l"(Bs_ + (size_t)row_ * ldb + seg_ * 8)); } \
    asm volatile("cp.async.commit_group;"); }

    int nkb = K >> 6;
    ISSUE_B(0, 0);
    ISSUE_B(1, 1);

    unsigned arow = (unsigned)(warp_m * 64 + (lane & 7) + (lane & 8));
    unsigned acol = (lane & 16) ? 16u : 0u;
    unsigned brow = (unsigned)(warp_n * 64 + (lane & 7) + ((lane & 16) >> 1));
    unsigned bcol = (lane & 8) ? 16u : 0u;

    for (int kb = 0; kb < nkb; kb++) {
        int st = kb % 3;
        asm volatile("cp.async.wait_group 1;" ::: "memory");
        __syncthreads();
        unsigned ab_ = sbase + st * 32768u;
        unsigned bb_ = sbase + 98304u + st * 16384u;
        #pragma unroll
        for (int k16 = 0; k16 < 4; k16++) {
            unsigned kc = k16 * 32u;
            unsigned af[4][4], bf[4][4];
            #pragma unroll
            for (int mi = 0; mi < 4; mi++)
                LDMX4(af[mi], ab_ + swz((arow + mi * 16u) * 128u + kc + acol));
            #pragma unroll
            for (int pi = 0; pi < 4; pi++)
                LDMX4(bf[pi], bb_ + swz((brow + pi * 16u) * 128u + kc + bcol));
            #pragma unroll
            for (int mi = 0; mi < 4; mi++)
                #pragma unroll
                for (int pi = 0; pi < 4; pi++) {
                    MMAB(acc[mi][2*pi],   af[mi], bf[pi][0], bf[pi][1]);
                    MMAB(acc[mi][2*pi+1], af[mi], bf[pi][2], bf[pi][3]);
                }
        }
        if (kb + 2 < nkb) { ISSUE_B((kb + 2) % 3, kb + 2); }
        else asm volatile("cp.async.commit_group;");
    }

    int g = lane >> 2, t = lane & 3;
    if (n0 < 512) {
        #pragma unroll
        for (int mi = 0; mi < 4; mi++) {
            #pragma unroll
            for (int r = 0; r < 2; r++) {
                int m = m0 + warp_m * 64 + mi * 16 + g + r * 8;
                #pragma unroll
                for (int ni = 0; ni < 8; ni++) {
                    int n = n0 + warp_n * 64 + ni * 8 + 2 * t;
                    __nv_bfloat16* Yp = Yb + sY * b + (size_t)m * ldy + n;
                    *(__nv_bfloat162*)Yp = __floats2bfloat162_rn(acc[mi][ni][2*r], acc[mi][ni][2*r+1]);
                }
            }
        }
    } else {
        __syncthreads();
        unsigned short* sw = (unsigned short*)smem + wid * (64 * 65);
        #pragma unroll
        for (int mi = 0; mi < 4; mi++) {
            #pragma unroll
            for (int r = 0; r < 2; r++) {
                int ml = mi * 16 + g + r * 8;
                #pragma unroll
                for (int ni = 0; ni < 8; ni++) {
                    int nl = ni * 8 + 2 * t;
                    __nv_bfloat162 p = __floats2bfloat162_rn(acc[mi][ni][2*r], acc[mi][ni][2*r+1]);
                    sw[ml * 65 + nl]     = ((unsigned short*)&p)[0];
                    sw[ml * 65 + nl + 1] = ((unsigned short*)&p)[1];
                }
            }
        }
        __syncwarp();
        int d_base = n0 - 512 + warp_n * 64;
        int t_base = m0 + warp_m * 64;
        unsigned short* Vb = (unsigned short*)(Vt + (size_t)b * CHW);
        for (int row = 0; row < 64; row++) {
            unsigned short w0 = sw[(lane * 2) * 65 + row];
            unsigned short w1 = sw[(lane * 2 + 1) * 65 + row];
            unsigned v = (unsigned)w0 | ((unsigned)w1 << 16);
            *(unsigned*)&Vb[(size_t)(d_base + row) * 4096 + t_base + lane * 2] = v;
        }
    }
}

// ====== bf16 out-projection GEMM, NCHW transposed epilogue; grid (16, 2, BB), K=256 ======
__global__ void __launch_bounds__(256, 1) gemm_out(
    const __nv_bfloat16* __restrict__ A,
    const __nv_bfloat16* __restrict__ B,
    float* __restrict__ Y,
    const float* __restrict__ bias, const float* __restrict__ res)
{
    extern __shared__ char smem[];
    unsigned sbase = smem_u32(smem);
    int tid = threadIdx.x, lane = tid & 31, wid = tid >> 5;
    int warp_m = wid & 3, warp_n = wid >> 2;
    int b = blockIdx.z;
    int m0 = blockIdx.x * 256, n0 = blockIdx.y * 128;
    const __nv_bfloat16* Ab = A + (size_t)b * CHW + (size_t)m0 * 256;
    const __nv_bfloat16* Bb = B + (size_t)n0 * 256;

    float acc[4][8][4];
    #pragma unroll
    for (int mi = 0; mi < 4; mi++)
        #pragma unroll
        for (int ni = 0; ni < 8; ni++)
            #pragma unroll
            for (int e = 0; e < 4; e++) acc[mi][ni][e] = 0.f;

#define ISSUE_O(st, kb) { \
    unsigned ab_ = sbase + (st) * 32768u; \
    unsigned bb_ = sbase + 98304u + (st) * 16384u; \
    const __nv_bfloat16* As_ = Ab + (kb) * 64; \
    const __nv_bfloat16* Bs_ = Bb + (kb) * 64; \
    _Pragma("unroll") \
    for (int i_ = 0; i_ < 8; i_++) { \
        int c_ = tid + i_ * 256; int row_ = c_ >> 3, seg_ = c_ & 7; \
        unsigned d_ = ab_ + swz((unsigned)row_ * 128u + seg_ * 16u); \
        asm volatile("cp.async.cg.shared.global [%0], [%1], 16;" :: "r"(d_), "l"(As_ + (size_t)row_ * 256 + seg_ * 8)); } \
    _Pragma("unroll") \
    for (int i_ = 0; i_ < 4; i_++) { \
        int c_ = tid + i_ * 256; int row_ = c_ >> 3, seg_ = c_ & 7; \
        unsigned d_ = bb_ + swz((unsigned)row_ * 128u + seg_ * 16u); \
        asm volatile("cp.async.cg.shared.global [%0], [%1], 16;" :: "r"(d_), "l"(Bs_ + (size_t)row_ * 256 + seg_ * 8)); } \
    asm volatile("cp.async.commit_group;"); }

    ISSUE_O(0, 0);
    ISSUE_O(1, 1);

    unsigned arow = (unsigned)(warp_m * 64 + (lane & 7) + (lane & 8));
    unsigned acol = (lane & 16) ? 16u : 0u;
    unsigned brow = (unsigned)(warp_n * 64 + (lane & 7) + ((lane & 16) >> 1));
    unsigned bcol = (lane & 8) ? 16u : 0u;

    for (int kb = 0; kb < 4; kb++) {
        int st = kb % 3;
        asm volatile("cp.async.wait_group 1;" ::: "memory");
        __syncthreads();
        unsigned ab_ = sbase + st * 32768u;
        unsigned bb_ = sbase + 98304u + st * 16384u;
        #pragma unroll
        for (int k16 = 0; k16 < 4; k16++) {
            unsigned kc = k16 * 32u;
            unsigned af[4][4], bf[4][4];
            #pragma unroll
            for (int mi = 0; mi < 4; mi++)
                LDMX4(af[mi], ab_ + swz((arow + mi * 16u) * 128u + kc + acol));
            #pragma unroll
            for (int pi = 0; pi < 4; pi++)
                LDMX4(bf[pi], bb_ + swz((brow + pi * 16u) * 128u + kc + bcol));
            #pragma unroll
            for (int mi = 0; mi < 4; mi++)
                #pragma unroll
                for (int pi = 0; pi < 4; pi++) {
                    MMAB(acc[mi][2*pi],   af[mi], bf[pi][0], bf[pi][1]);
                    MMAB(acc[mi][2*pi+1], af[mi], bf[pi][2], bf[pi][3]);
                }
        }
        if (kb + 2 < 4) { ISSUE_O((kb + 2) % 3, kb + 2); }
        else asm volatile("cp.async.commit_group;");
    }

    __syncthreads();
    float* sw = (float*)smem + wid * (64 * 65);
    const float* Rb = res + (size_t)b * CHW;
    int g = lane >> 2, t = lane & 3;
    #pragma unroll
    for (int mi = 0; mi < 4; mi++) {
        #pragma unroll
        for (int r = 0; r < 2; r++) {
            int ml = mi * 16 + g + r * 8;
            int m = m0 + warp_m * 64 + ml;
            #pragma unroll
            for (int ni = 0; ni < 8; ni++) {
                int nl = ni * 8 + 2 * t;
                int n = n0 + warp_n * 64 + nl;
                sw[ml * 65 + nl]     = acc[mi][ni][2*r]     + bias[n]     + Rb[(size_t)m * 256 + n];
                sw[ml * 65 + nl + 1] = acc[mi][ni][2*r + 1] + bias[n + 1] + Rb[(size_t)m * 256 + n + 1];
            }
        }
    }
    __syncwarp();
    int m_base = m0 + warp_m * 64, n_base = n0 + warp_n * 64;
    float* Yb_ = Y + (size_t)b * CHW;
    for (int row = 0; row < 64; row++) {
        float2 w = make_float2(sw[(lane * 2) * 65 + row], sw[(lane * 2 + 1) * 65 + row]);
        *(float2*)&Yb_[(size_t)(n_base + row) * 4096 + m_base + lane * 2] = w;
    }
}

// ====== fused flash attention (bf16); grid (32, BB), block 512 ======
#define FA_SQ 0u
#define FA_SK 65536u
#define FA_SV 131072u
#define FA_SP 196608u
#define FA_SM 212992u
#define FA_SL 213504u
#define FA_RM 214016u
#define FA_RS 215040u
#define FA_SMEM 216064
__global__ void __launch_bounds__(512, 1) flash_attn(
    const __nv_bfloat16* __restrict__ qkv, const __nv_bfloat16* __restrict__ vt,
    __nv_bfloat16* __restrict__ ao)
{
    extern __shared__ char smem[];
    unsigned sb = smem_u32(smem);
    float* fSM = (float*)(smem + FA_SM);
    float* fSL = (float*)(smem + FA_SL);
    float* fRM = (float*)(smem + FA_RM);
    float* fRS = (float*)(smem + FA_RS);
    int tid = threadIdx.x, lane = tid & 31, wid = tid >> 5;
    int warp_m = wid & 7, warp_n = wid >> 3;
    int b = blockIdx.y, q0 = blockIdx.x * 128;
    const __nv_bfloat16* qb = qkv + (size_t)b * 3 * CHW;
    const __nv_bfloat16* kb = qb + 256;
    const __nv_bfloat16* vb = vt + (size_t)b * CHW;
    int g = lane >> 2, t = lane & 3;
    unsigned arow_l = (unsigned)((lane & 7) + (lane & 8));
    unsigned acol = (lane & 16) ? 16u : 0u;
    unsigned brow_l = (unsigned)((lane & 7) + ((lane & 16) >> 1));
    unsigned bcol = (lane & 8) ? 16u : 0u;

#define PAIR_BAR() asm volatile("bar.sync %0, 64;" :: "r"(1 + warp_m) : "memory")

#define FA_KV(bufv, jv) { \
    _Pragma("unroll") \
    for (int i_ = 0; i_ < 4; i_++) { \
        int idx = tid + i_ * 512; int ch = idx >> 9, row = (idx >> 3) & 63, seg = idx & 7; \
        unsigned d_ = sb + FA_SK + (bufv) * 32768u + ch * 8192u + swz((unsigned)row * 128u + seg * 16u); \
        const __nv_bfloat16* s_ = kb + (size_t)((jv) + row) * 768 + ch * 64 + seg * 8; \
        asm volatile("cp.async.cg.shared.global [%0], [%1], 16;" :: "r"(d_), "l"(s_)); } \
    _Pragma("unroll") \
    for (int i_ = 0; i_ < 4; i_++) { \
        int idx = tid + i_ * 512; int row = idx >> 3, seg = idx & 7; \
        unsigned d_ = sb + FA_SV + (bufv) * 32768u + swz((unsigned)row * 128u + seg * 16u); \
        const __nv_bfloat16* s_ = vb + (size_t)row * 4096 + (jv) + seg * 8; \
        asm volatile("cp.async.cg.shared.global [%0], [%1], 16;" :: "r"(d_), "l"(s_)); } }

    #pragma unroll
    for (int i_ = 0; i_ < 8; i_++) {
        int idx = tid + i_ * 512; int ch = idx >> 10, row = (idx >> 3) & 127, seg = idx & 7;
        unsigned d_ = sb + FA_SQ + ch * 16384u + swz((unsigned)row * 128u + seg * 16u);
        const __nv_bfloat16* s_ = qb + (size_t)(q0 + row) * 768 + ch * 64 + seg * 8;
        asm volatile("cp.async.cg.shared.global [%0], [%1], 16;" :: "r"(d_), "l"(s_));
    }
    FA_KV(0, 0);
    asm volatile("cp.async.commit_group;");
    FA_KV(1, 64);
    asm volatile("cp.async.commit_group;");
    if (tid < 128) { fSM[tid] = -1e30f; fSL[tid] = 0.f; }

    float accO[16][4];
    #pragma unroll
    for (int ni = 0; ni < 16; ni++)
        #pragma unroll
        for (int e = 0; e < 4; e++) accO[ni][e] = 0.f;

    int r0 = warp_m * 16 + g, r1 = r0 + 8;

    for (int it = 0; it < 64; it++) {
        int buf = it & 1;
        asm volatile("cp.async.wait_group 1;" ::: "memory");
        __syncthreads();
        float accS[4][4];
        #pragma unroll
        for (int ni = 0; ni < 4; ni++)
            #pragma unroll
            for (int e = 0; e < 4; e++) accS[ni][e] = 0.f;
        unsigned kbase = sb + FA_SK + buf * 32768u;
        #pragma unroll
        for (int kst = 0; kst < 16; kst++) {
            unsigned ch = kst >> 2, kc = (kst & 3) * 32u;
            unsigned af[4], bf0[4], bf1[4];
            LDMX4(af, sb + FA_SQ + ch * 16384u + swz((warp_m * 16 + arow_l) * 128u + kc + acol));
            LDMX4(bf0, kbase + ch * 8192u + swz((warp_n * 32 + brow_l) * 128u + kc + bcol));
            LDMX4(bf1, kbase + ch * 8192u + swz((warp_n * 32 + 16 + brow_l) * 128u + kc + bcol));
            MMAB(accS[0], af, bf0[0], bf0[1]); MMAB(accS[1], af, bf0[2], bf0[3]);
            MMAB(accS[2], af, bf1[0], bf1[1]); MMAB(accS[3], af, bf1[2], bf1[3]);
        }
        #pragma unroll
        for (int ni = 0; ni < 4; ni++)
            #pragma unroll
            for (int e = 0; e < 4; e++) accS[ni][e] *= 0.0625f;
        float pm0 = -1e30f, pm1 = -1e30f;
        #pragma unroll
        for (int ni = 0; ni < 4; ni++) {
            pm0 = fmaxf(pm0, fmaxf(accS[ni][0], accS[ni][1]));
            pm1 = fmaxf(pm1, fmaxf(accS[ni][2], accS[ni][3]));
        }
        pm0 = fmaxf(pm0, __shfl_xor_sync(~0u, pm0, 1)); pm0 = fmaxf(pm0, __shfl_xor_sync(~0u, pm0, 2));
        pm1 = fmaxf(pm1, __shfl_xor_sync(~0u, pm1, 1)); pm1 = fmaxf(pm1, __shfl_xor_sync(~0u, pm1, 2));
        if (t == 0) { fRM[warp_n * 128 + r0] = pm0; fRM[warp_n * 128 + r1] = pm1; }
        PAIR_BAR();
        float mo0 = fSM[r0], mo1 = fSM[r1];
        float mn0 = fmaxf(mo0, fmaxf(fRM[r0], fRM[128 + r0]));
        float mn1 = fmaxf(mo1, fmaxf(fRM[r1], fRM[128 + r1]));
        float al0 = __expf(mo0 - mn0), al1 = __expf(mo1 - mn1);
        float ps0 = 0.f, ps1 = 0.f;
        #pragma unroll
        for (int ni = 0; ni < 4; ni++) {
            float p00 = __expf(accS[ni][0] - mn0), p01 = __expf(accS[ni][1] - mn0);
            float p10 = __expf(accS[ni][2] - mn1), p11 = __expf(accS[ni][3] - mn1);
            ps0 += p00 + p01; ps1 += p10 + p11;
            unsigned col2 = (unsigned)(warp_n * 32 + ni * 8 + 2 * t) * 2u;
            *(__nv_bfloat162*)(smem + FA_SP + swz((unsigned)r0 * 128u + col2)) = __floats2bfloat162_rn(p00, p01);
            *(__nv_bfloat162*)(smem + FA_SP + swz((unsigned)r1 * 128u + col2)) = __floats2bfloat162_rn(p10, p11);
        }
        ps0 += __shfl_xor_sync(~0u, ps0, 1); ps0 += __shfl_xor_sync(~0u, ps0, 2);
        ps1 += __shfl_xor_sync(~0u, ps1, 1); ps1 += __shfl_xor_sync(~0u, ps1, 2);
        if (t == 0) { fRS[warp_n * 128 + r0] = ps0; fRS[warp_n * 128 + r1] = ps1; }
        #pragma unroll
        for (int ni = 0; ni < 16; ni++) {
            accO[ni][0] *= al0; accO[ni][1] *= al0;
            accO[ni][2] *= al1; accO[ni][3] *= al1;
        }
        PAIR_BAR();
        if (warp_n == 0 && t == 0) {
            fSM[r0] = mn0;
            fSL[r0] = fSL[r0] * al0 + fRS[r0] + fRS[128 + r0];
            fSM[r1] = mn1;
            fSL[r1] = fSL[r1] * al1 + fRS[r1] + fRS[128 + r1];
        }
        unsigned vbase = sb + FA_SV + buf * 32768u;
        #pragma unroll
        for (int kst = 0; kst < 4; kst++) {
            unsigned kc = kst * 32u;
            unsigned af[4];
            LDMX4(af, sb + FA_SP + swz((warp_m * 16 + arow_l) * 128u + kc + acol));
            #pragma unroll
            for (int pi = 0; pi < 8; pi++) {
                unsigned bf[4];
                LDMX4(bf, vbase + swz((warp_n * 128 + pi * 16 + brow_l) * 128u + kc + bcol));
                MMAB(accO[2*pi],   af, bf[0], bf[1]);
                MMAB(accO[2*pi+1], af, bf[2], bf[3]);
            }
        }
        __syncthreads();
        int jn = (it + 2) * 64;
        if (jn < 4096) { FA_KV(buf, jn); }
        asm volatile("cp.async.commit_group;");
    }
    float il0 = 1.f / fSL[r0], il1 = 1.f / fSL[r1];
    __nv_bfloat16* o0 = ao + (size_t)b * CHW + (size_t)(q0 + r0) * 256;
    __nv_bfloat16* o1 = ao + (size_t)b * CHW + (size_t)(q0 + r1) * 256;
    #pragma unroll
    for (int ni = 0; ni < 16; ni++) {
        int dcol = warp_n * 128 + ni * 8 + 2 * t;
        *(__nv_bfloat162*)(o0 + dcol) = __floats2bfloat162_rn(accO[ni][0] * il0, accO[ni][1] * il0);
        *(__nv_bfloat162*)(o1 + dcol) = __floats2bfloat162_rn(accO[ni][2] * il1, accO[ni][3] * il1);
    }
}

// ====== GroupNorm partial stats: grid BB*32*4, block 256; part[blk]=(sum, sq) ======
template<int NCHW>
__global__ void gn_part(const float* __restrict__ x, float* __restrict__ part) {
    __shared__ float rsh[256], rqh[256];
    int blk = blockIdx.x;
    int bg = blk >> 2, ck = blk & 3;
    int b = bg >> 5, grp = bg & 31;
    int tid = threadIdx.x;
    float sum = 0.f, sq = 0.f;
    if (NCHW) {
        const float4* x4 = (const float4*)(x + (size_t)b * CHW + (size_t)grp * 8 * 4096) + ck * 2048;
        for (int i = tid; i < 2048; i += 256) {
            float4 v = x4[i];
            sum += (v.x + v.y) + (v.z + v.w);
            sq += v.x*v.x + v.y*v.y + v.z*v.z + v.w*v.w;
        }
    } else {
        const float* xp = x + (size_t)b * CHW + grp * 8 + (size_t)ck * 1024 * 256;
        for (int i = tid; i < 1024; i += 256) {
            float4 v0 = *(const float4*)&xp[(size_t)i * 256];
            float4 v1 = *(const float4*)&xp[(size_t)i * 256 + 4];
            sum += (v0.x+v0.y)+(v0.z+v0.w)+(v1.x+v1.y)+(v1.z+v1.w);
            sq += v0.x*v0.x+v0.y*v0.y+v0.z*v0.z+v0.w*v0.w+v1.x*v1.x+v1.y*v1.y+v1.z*v1.z+v1.w*v1.w;
        }
    }
    rsh[tid] = sum; rqh[tid] = sq;
    __syncthreads();
    for (int st = 128; st > 0; st >>= 1) {
        if (tid < st) { rsh[tid] += rsh[tid+st]; rqh[tid] += rqh[tid+st]; }
        __syncthreads();
    }
    if (tid == 0) { part[blk * 2] = rsh[0]; part[blk * 2 + 1] = rqh[0]; }
}

__device__ __forceinline__ void gn_minv(const float* part, int bg, float& m, float& inv) {
    float s = (part[(bg*4)*2]   + part[(bg*4+1)*2])   + (part[(bg*4+2)*2]   + part[(bg*4+3)*2]);
    float q = (part[(bg*4)*2+1] + part[(bg*4+1)*2+1]) + (part[(bg*4+2)*2+1] + part[(bg*4+3)*2+1]);
    m = s * (1.f/32768.f);
    inv = rsqrtf(q * (1.f/32768.f) - m*m + 1e-5f);
}

// ====== GroupNorm apply from NCHW -> NHWC tf32 f32 (+SiLU); grid BB*32*4, block 256 ======
__global__ void gn_apply_nchw(const float* __restrict__ x, const float* __restrict__ sc,
                              const float* __restrict__ bi, const float* __restrict__ part,
                              float* __restrict__ y) {
    int bg = blockIdx.x >> 2, ck = blockIdx.x & 3;
    int b = bg >> 5, grp = bg & 31;
    const float* xp = x + (size_t)b * CHW + (size_t)grp * 8 * 4096;
    float m, inv;
    gn_minv(part, bg, m, inv);
    float aa[8], bb[8];
    #pragma unroll
    for (int c = 0; c < 8; c++) { aa[c] = inv * sc[grp*8+c]; bb[c] = bi[grp*8+c] - m * aa[c]; }
    int p0 = ck * 1024;
    for (int p = p0 + threadIdx.x; p < p0 + 1024; p += 256) {
        float v[8];
        #pragma unroll
        for (int c = 0; c < 8; c++) {
            float tv = xp[(size_t)c * 4096 + p] * aa[c] + bb[c];
            tv = tv / (1.f + __expf(-tv));
            v[c] = rnd_tf32(tv);
        }
        float* yp = y + (size_t)b * CHW + (size_t)p * 256 + grp * 8;
        *(float4*)yp       = make_float4(v[0],v[1],v[2],v[3]);
        *(float4*)(yp + 4) = make_float4(v[4],v[5],v[6],v[7]);
    }
}

// ====== GroupNorm apply NHWC (+opt SiLU); OUT16=0 tf32 f32, OUT16=1 bf16; grid BB*32*4, block 256
template<int OUT16>
__global__ void gn_apply_nhwc(const float* __restrict__ x, const float* __restrict__ sc,
                              const float* __restrict__ bi, const float* __restrict__ part,
                              void* __restrict__ yv, int dosilu) {
    int bg = blockIdx.x >> 2, ck = blockIdx.x & 3;
    int b = bg >> 5, grp = bg & 31;
    const float* xp = x + (size_t)b * CHW + grp * 8;
    float m, inv;
    gn_minv(part, bg, m, inv);
    float aa[8], bb[8];
    #pragma unroll
    for (int j = 0; j < 8; j++) { aa[j] = inv * sc[grp*8+j]; bb[j] = bi[grp*8+j] - m * aa[j]; }
    int p0 = ck * 1024;
    for (int i = p0 + threadIdx.x; i < p0 + 1024; i += 256) {
        float4 v0 = *(const float4*)&xp[(size_t)i * 256];
        float4 v1 = *(const float4*)&xp[(size_t)i * 256 + 4];
        float v[8] = { v0.x,v0.y,v0.z,v0.w,v1.x,v1.y,v1.z,v1.w };
        #pragma unroll
        for (int j = 0; j < 8; j++) {
            float tv = v[j]*aa[j] + bb[j];
            if (dosilu) tv = tv / (1.f + __expf(-tv));
            v[j] = tv;
        }
        if (OUT16) {
            __nv_bfloat16* yp = (__nv_bfloat16*)yv + (size_t)b * CHW + grp * 8 + (size_t)i * 256;
            __nv_bfloat162 o[4];
            #pragma unroll
            for (int j = 0; j < 4; j++) o[j] = __floats2bfloat162_rn(v[2*j], v[2*j+1]);
            *(uint4*)yp = *(uint4*)o;
        } else {
            float* yp = (float*)yv + (size_t)b * CHW + grp * 8 + (size_t)i * 256;
            #pragma unroll
            for (int j = 0; j < 8; j++) v[j] = rnd_tf32(v[j]);
            *(float4*)yp       = make_float4(v[0],v[1],v[2],v[3]);
            *(float4*)(yp + 4) = make_float4(v[4],v[5],v[6],v[7]);
        }
    }
}

// both conv weights; grid (9, 512), block 256
__global__ void wtrans2(const float* __restrict__ w1, const float* __restrict__ w2,
                        float* __restrict__ wt1, float* __restrict__ wt2) {
    int o = blockIdx.y;
    int ko = blockIdx.x * 256 + threadIdx.x;
    const float* w = (o < 256) ? w1 : w2;
    float* wt = (o < 256) ? wt1 : wt2;
    int oo = o & 255;
    wt[(size_t)oo * KC + ko] = rnd_tf32(w[(size_t)oo * KC + (ko & 255) * 9 + (ko >> 8)]);
}

// qkv_w + out_w -> bf16; grid 1024, block 256
__global__ void wcast_bf(const float* __restrict__ qw, const float* __restrict__ ow,
                         __nv_bfloat16* __restrict__ qwb, __nv_bfloat16* __restrict__ owb) {
    int i = blockIdx.x * 256 + threadIdx.x;
    if (i < 768 * 256) qwb[i] = __float2bfloat16(qw[i]);
    else owb[i - 768 * 256] = __float2bfloat16(ow[i - 768 * 256]);
}

// grid (BB, 4), block 128
__global__ void film_mlp(const float* __restrict__ te, const float* __restrict__ w,
                         const float* __restrict__ bi, float* __restrict__ gb) {
    __shared__ float s_te[256];
    int b = blockIdx.x, tid = threadIdx.x;
    for (int i = tid; i < 256; i += 128) {
        float v = te[b * 256 + i];
        s_te[i] = v / (1.f + __expf(-v));
    }
    __syncthreads();
    int j = blockIdx.y * 128 + tid;
    const float* wr = w + (size_t)j * 256;
    float acc = bi[j];
    for (int t = 0; t < 256; t++) acc += s_te[t] * wr[t];
    gb[b * 512 + j] = acc;
}

extern "C" void kernel_launch(void* const* d_in, const int* in_sizes, int n_in,
                              void* d_out, int out_size) {
    const float* x = (const float*)d_in[0];
    const float* te = (const float*)d_in[1];
    const float* gn1_s = (const float*)d_in[2];
    const float* gn1_b = (const float*)d_in[3];
    const float* conv1_w = (const float*)d_in[4];
    const float* conv1_b = (const float*)d_in[5];
    const float* mlp_w = (const float*)d_in[6];
    const float* mlp_b = (const float*)d_in[7];
    const float* gn2_s = (const float*)d_in[8];
    const float* gn2_b = (const float*)d_in[9];
    const float* conv2_w = (const float*)d_in[10];
    const float* conv2_b = (const float*)d_in[11];
    const float* gnA_s = (const float*)d_in[12];
    const float* gnA_b = (const float*)d_in[13];
    const float* qkv_w = (const float*)d_in[14];
    const float* out_w = (const float*)d_in[15];
    const float* out_b = (const float*)d_in[16];
    float* out = (float*)d_out;

    float *a,*h,*xr,*gb,*part,*w1t,*w2t;
    __nv_bfloat16 *ah,*qwb,*owb,*qkvb,*vtb,*aob;
    cudaGetSymbolAddress((void**)&a, g_a);    cudaGetSymbolAddress((void**)&h, g_h);
    cudaGetSymbolAddress((void**)&xr, g_xr);  cudaGetSymbolAddress((void**)&gb, g_gb);
    cudaGetSymbolAddress((void**)&part, g_part);
    cudaGetSymbolAddress((void**)&w1t, g_w1t);cudaGetSymbolAddress((void**)&w2t, g_w2t);
    cudaGetSymbolAddress((void**)&ah, g_ah);  cudaGetSymbolAddress((void**)&qwb, g_qwb);
    cudaGetSymbolAddress((void**)&owb, g_owb);cudaGetSymbolAddress((void**)&qkvb, g_qkvb);
    cudaGetSymbolAddress((void**)&vtb, g_vtb);cudaGetSymbolAddress((void**)&aob, g_aob);

    static int init_done = 0;
    static cudaStream_t s2;
    static cudaEvent_t ev0, ev1;
    if (!init_done) {
        cudaFuncSetAttribute(gemm_conv, cudaFuncAttributeMaxDynamicSharedMemorySize, 196608);
        cudaFuncSetAttribute(gemm_bf, cudaFuncAttributeMaxDynamicSharedMemorySize, 147456);
        cudaFuncSetAttribute(gemm_out, cudaFuncAttributeMaxDynamicSharedMemorySize, 147456);
        cudaFuncSetAttribute(flash_attn, cudaFuncAttributeMaxDynamicSharedMemorySize, FA_SMEM);
        cudaStreamCreate(&s2);
        cudaEventCreateWithFlags(&ev0, cudaEventDisableTiming);
        cudaEventCreateWithFlags(&ev1, cudaEventDisableTiming);
        init_done = 1;
    }
    const float* NUL = (const float*)0;

    // fork: setup kernels on side stream, overlapped with gn1
    cudaEventRecord(ev0, 0);
    cudaStreamWaitEvent(s2, ev0, 0);
    film_mlp<<<dim3(BB, 4), 128, 0, s2>>>(te, mlp_w, mlp_b, gb);
    wtrans2<<<dim3(9, 512), 256, 0, s2>>>(conv1_w, conv2_w, w1t, w2t);
    wcast_bf<<<1024, 256, 0, s2>>>(qkv_w, out_w, qwb, owb);
    cudaEventRecord(ev1, s2);

    // gn1: NCHW partial stats + apply
    gn_part<1><<<BB*32*4, 256>>>(x, part);
    gn_apply_nchw<<<BB*32*4, 256>>>(x, gn1_s, gn1_b, part, a);
    cudaStreamWaitEvent(0, ev1, 0);

    // conv1 (implicit im2col) + bias + FiLM
    gemm_conv<<<dim3(16, 2, BB), 256, 196608>>>(a, w1t, h, conv1_b, gb, NUL);

    // conv2 + bias + x residual (NCHW)
    gn_part<0><<<BB*32*4, 256>>>(h, part);
    gn_apply_nhwc<0><<<BB*32*4, 256>>>(h, gn2_s, gn2_b, part, a, 1);
    gemm_conv<<<dim3(16, 2, BB), 256, 196608>>>(a, w2t, xr, conv2_b, NUL, x);

    // attention (all bf16); qkv GEMM writes Q/K to qkvb and V transposed into vtb
    gn_part<0><<<BB*32*4, 256>>>(xr, part);
    gn_apply_nhwc<1><<<BB*32*4, 256>>>(xr, gnA_s, gnA_b, part, ah, 0);
    gemm_bf<<<dim3(16, 6, BB), 256, 147456>>>(ah, 256, CHW, qwb, 256, qkvb, 768, 3*CHW, 256, vtb);
    flash_attn<<<dim3(32, BB), 512, FA_SMEM>>>(qkvb, vtb, aob);
    gemm_out<<<dim3(16, 2, BB), 256, 147456>>>(aob, owb, out, out_b, xr);
}